// round 2
// baseline (speedup 1.0000x reference)
#include <cuda_runtime.h>
#include <math.h>

#define S_LEN   2048
#define D_MODEL 1024
#define NH      16
#define DH      64
#define BATCH   2
#define M_ROWS  (BATCH * S_LEN)   // 4096

// ---------------------------------------------------------------------------
// Scratch (device globals: allocation-free, graph-capture safe)
// ---------------------------------------------------------------------------
__device__ float g_q[M_ROWS * D_MODEL];
__device__ float g_k[M_ROWS * D_MODEL];
__device__ float g_v[M_ROWS * D_MODEL];
__device__ float g_att[M_ROWS * D_MODEL];

// ---------------------------------------------------------------------------
// SGEMM: Y[M,N] = X[M,K] @ W[N,K]^T   (torch Linear convention)
// BM=BN=64, BK=16, 256 threads, 4x4 micro-tile per thread.
// ---------------------------------------------------------------------------
__global__ __launch_bounds__(256) void sgemm_xwT(
    const float* __restrict__ X, const float* __restrict__ W,
    float* __restrict__ Y, int M, int N, int K)
{
    __shared__ __align__(16) float Xs[16][68];   // [k][m], padded row = 272B (16B mult)
    __shared__ __align__(16) float Ws[16][68];   // [k][n]

    const int tid  = threadIdx.x;
    const int tx   = tid & 15;        // 0..15 -> N micro
    const int ty   = tid >> 4;        // 0..15 -> M micro
    const int row0 = blockIdx.y * 64;
    const int col0 = blockIdx.x * 64;

    // Cooperative loads: one float4 per thread per operand per k-tile
    const int lr = tid >> 2;          // 0..63 tile row
    const int lk = (tid & 3) * 4;     // 0,4,8,12 along K
    const float* Xp = X + (size_t)(row0 + lr) * K + lk;
    const float* Wp = W + (size_t)(col0 + lr) * K + lk;

    float acc[4][4] = {};

    for (int k0 = 0; k0 < K; k0 += 16) {
        float4 xv = *(const float4*)(Xp + k0);
        float4 wv = *(const float4*)(Wp + k0);
        Xs[lk + 0][lr] = xv.x; Xs[lk + 1][lr] = xv.y;
        Xs[lk + 2][lr] = xv.z; Xs[lk + 3][lr] = xv.w;
        Ws[lk + 0][lr] = wv.x; Ws[lk + 1][lr] = wv.y;
        Ws[lk + 2][lr] = wv.z; Ws[lk + 3][lr] = wv.w;
        __syncthreads();

        #pragma unroll
        for (int k = 0; k < 16; k++) {
            float4 a = *(const float4*)&Xs[k][ty * 4];
            float4 b = *(const float4*)&Ws[k][tx * 4];
            float ar[4] = {a.x, a.y, a.z, a.w};
            float br[4] = {b.x, b.y, b.z, b.w};
            #pragma unroll
            for (int i = 0; i < 4; i++)
                #pragma unroll
                for (int j = 0; j < 4; j++)
                    acc[i][j] = fmaf(ar[i], br[j], acc[i][j]);
        }
        __syncthreads();
    }

    #pragma unroll
    for (int i = 0; i < 4; i++) {
        float4 o = make_float4(acc[i][0], acc[i][1], acc[i][2], acc[i][3]);
        *(float4*)(Y + (size_t)(row0 + ty * 4 + i) * N + col0 + tx * 4) = o;
    }
}

// ---------------------------------------------------------------------------
// Flash attention (causal), fp32. One block per (q-tile=64, head, batch).
// 256 threads, 16x16 grid, each thread owns a 4x4 patch of the 64x64 score
// tile and a 4x4 patch of the 64x64 output tile. Q/K staged d-major in smem,
// P staged through smem for the PV product.
// ---------------------------------------------------------------------------
__global__ __launch_bounds__(256) void attn_fwd(
    const float* __restrict__ Qg, const float* __restrict__ Kg,
    const float* __restrict__ Vg, float* __restrict__ Og)
{
    extern __shared__ __align__(16) float smem[];
    float (*Qs)[68] = (float(*)[68])(smem);              // [d][i]
    float (*Ks)[68] = (float(*)[68])(smem + 1 * 64 * 68);// [d][j]
    float (*Vs)[68] = (float(*)[68])(smem + 2 * 64 * 68);// [j][c]
    float (*Ps)[68] = (float(*)[68])(smem + 3 * 64 * 68);// [i][j]

    const int tid = threadIdx.x;
    const int tx  = tid & 15;          // key / out-col micro
    const int ty  = tid >> 4;          // query-row micro
    const int qt  = blockIdx.x;
    const int q0  = qt * 64;
    const int h   = blockIdx.y;
    const int b   = blockIdx.z;

    const float* Qb = Qg + ((size_t)b * S_LEN + q0) * D_MODEL + h * DH;
    const float* Kb = Kg + (size_t)b * S_LEN * D_MODEL + h * DH;
    const float* Vb = Vg + (size_t)b * S_LEN * D_MODEL + h * DH;

    // Load Q tile transposed (d-major) with the 1/sqrt(DH) scale folded in
    #pragma unroll
    for (int r = 0; r < 4; r++) {
        int idx = tid + r * 256;           // 0..1023 float4 slots
        int row = idx >> 4;                // 0..63
        int c4  = (idx & 15) * 4;          // 0..60
        float4 qv = *(const float4*)(Qb + (size_t)row * D_MODEL + c4);
        Qs[c4 + 0][row] = qv.x * 0.125f;
        Qs[c4 + 1][row] = qv.y * 0.125f;
        Qs[c4 + 2][row] = qv.z * 0.125f;
        Qs[c4 + 3][row] = qv.w * 0.125f;
    }

    float m_i[4], l_i[4], o[4][4];
    #pragma unroll
    for (int i = 0; i < 4; i++) {
        m_i[i] = -INFINITY; l_i[i] = 0.f;
        #pragma unroll
        for (int j = 0; j < 4; j++) o[i][j] = 0.f;
    }

    for (int kt = 0; kt <= qt; kt++) {
        const int k0 = kt * 64;
        __syncthreads();   // previous iteration's Ps/Vs reads complete

        // Load K (transposed, d-major) and V (row-major) tiles
        #pragma unroll
        for (int r = 0; r < 4; r++) {
            int idx = tid + r * 256;
            int row = idx >> 4;
            int c4  = (idx & 15) * 4;
            float4 kv = *(const float4*)(Kb + (size_t)(k0 + row) * D_MODEL + c4);
            Ks[c4 + 0][row] = kv.x; Ks[c4 + 1][row] = kv.y;
            Ks[c4 + 2][row] = kv.z; Ks[c4 + 3][row] = kv.w;
            float4 vv = *(const float4*)(Vb + (size_t)(k0 + row) * D_MODEL + c4);
            *(float4*)&Vs[row][c4] = vv;
        }
        __syncthreads();

        // S = (Q*scale) @ K^T  : 4x4 per thread
        float s[4][4] = {};
        #pragma unroll
        for (int d = 0; d < 64; d++) {
            float4 qa = *(const float4*)&Qs[d][ty * 4];
            float4 kb = *(const float4*)&Ks[d][tx * 4];
            float ar[4] = {qa.x, qa.y, qa.z, qa.w};
            float br[4] = {kb.x, kb.y, kb.z, kb.w};
            #pragma unroll
            for (int i = 0; i < 4; i++)
                #pragma unroll
                for (int j = 0; j < 4; j++)
                    s[i][j] = fmaf(ar[i], br[j], s[i][j]);
        }

        // Causal mask only matters on the diagonal tile
        if (kt == qt) {
            #pragma unroll
            for (int i = 0; i < 4; i++)
                #pragma unroll
                for (int j = 0; j < 4; j++)
                    if (tx * 4 + j > ty * 4 + i) s[i][j] = -INFINITY;
        }

        // Online softmax update (row reduction across the 16 tx lanes)
        #pragma unroll
        for (int i = 0; i < 4; i++) {
            float mloc = fmaxf(fmaxf(s[i][0], s[i][1]), fmaxf(s[i][2], s[i][3]));
            #pragma unroll
            for (int off = 1; off < 16; off <<= 1)
                mloc = fmaxf(mloc, __shfl_xor_sync(0xffffffffu, mloc, off));
            float mnew  = fmaxf(m_i[i], mloc);
            float alpha = expf(m_i[i] - mnew);   // expf(-inf)=0 on first tile
            float psum = 0.f;
            #pragma unroll
            for (int j = 0; j < 4; j++) {
                float p = expf(s[i][j] - mnew);  // masked entries -> 0
                s[i][j] = p;
                psum += p;
            }
            #pragma unroll
            for (int off = 1; off < 16; off <<= 1)
                psum += __shfl_xor_sync(0xffffffffu, psum, off);
            l_i[i] = l_i[i] * alpha + psum;
            m_i[i] = mnew;
            #pragma unroll
            for (int j = 0; j < 4; j++) o[i][j] *= alpha;
            *(float4*)&Ps[ty * 4 + i][tx * 4] =
                make_float4(s[i][0], s[i][1], s[i][2], s[i][3]);
        }
        __syncthreads();

        // O += P @ V   (P broadcast from smem, V as float4 rows)
        #pragma unroll
        for (int j = 0; j < 64; j++) {
            float4 vv = *(const float4*)&Vs[j][tx * 4];
            #pragma unroll
            for (int i = 0; i < 4; i++) {
                float p = Ps[ty * 4 + i][j];
                o[i][0] = fmaf(p, vv.x, o[i][0]);
                o[i][1] = fmaf(p, vv.y, o[i][1]);
                o[i][2] = fmaf(p, vv.z, o[i][2]);
                o[i][3] = fmaf(p, vv.w, o[i][3]);
            }
        }
    }

    // Normalize and store (layout [B][S][D] so the Wo GEMM is standard)
    float* Ob = Og + ((size_t)b * S_LEN + q0) * D_MODEL + h * DH;
    #pragma unroll
    for (int i = 0; i < 4; i++) {
        float inv = 1.f / l_i[i];
        float4 ov = make_float4(o[i][0] * inv, o[i][1] * inv,
                                o[i][2] * inv, o[i][3] * inv);
        *(float4*)(Ob + (size_t)(ty * 4 + i) * D_MODEL + tx * 4) = ov;
    }
}

// ---------------------------------------------------------------------------
// Launch
// ---------------------------------------------------------------------------
extern "C" void kernel_launch(void* const* d_in, const int* in_sizes, int n_in,
                              void* d_out, int out_size)
{
    const float* x  = (const float*)d_in[0];
    const float* Wq = (const float*)d_in[1];
    const float* Wk = (const float*)d_in[2];
    const float* Wv = (const float*)d_in[3];
    const float* Wo = (const float*)d_in[4];
    float* out = (float*)d_out;

    float *q, *k, *v, *att;
    cudaGetSymbolAddress((void**)&q,   g_q);
    cudaGetSymbolAddress((void**)&k,   g_k);
    cudaGetSymbolAddress((void**)&v,   g_v);
    cudaGetSymbolAddress((void**)&att, g_att);

    dim3 gg(D_MODEL / 64, M_ROWS / 64);   // (16, 64)
    sgemm_xwT<<<gg, 256>>>(x, Wq, q, M_ROWS, D_MODEL, D_MODEL);
    sgemm_xwT<<<gg, 256>>>(x, Wk, k, M_ROWS, D_MODEL, D_MODEL);
    sgemm_xwT<<<gg, 256>>>(x, Wv, v, M_ROWS, D_MODEL, D_MODEL);

    const size_t smem = 4 * 64 * 68 * sizeof(float);  // 69632 B
    cudaFuncSetAttribute(attn_fwd, cudaFuncAttributeMaxDynamicSharedMemorySize,
                         (int)smem);
    attn_fwd<<<dim3(S_LEN / 64, NH, BATCH), 256, smem>>>(q, k, v, att);

    sgemm_xwT<<<gg, 256>>>(att, Wo, out, M_ROWS, D_MODEL, D_MODEL);
}

// round 3
// speedup vs baseline: 1.6678x; 1.6678x over previous
#include <cuda_runtime.h>
#include <math.h>
#include <stdint.h>

#define S_LEN   2048
#define D_MODEL 1024
#define NH      16
#define DH      64
#define BATCH   2
#define M_ROWS  (BATCH * S_LEN)   // 4096

// ---------------------------------------------------------------------------
// Scratch (device globals: allocation-free, graph-capture safe)
// ---------------------------------------------------------------------------
__device__ float g_q[M_ROWS * D_MODEL];
__device__ float g_k[M_ROWS * D_MODEL];
__device__ float g_v[M_ROWS * D_MODEL];
__device__ float g_att[M_ROWS * D_MODEL];

// ---------------------------------------------------------------------------
// tf32 helpers
// ---------------------------------------------------------------------------
__device__ __forceinline__ uint32_t f2tf32(float f) {
    uint32_t u;
    asm("cvt.rna.tf32.f32 %0, %1;" : "=r"(u) : "f"(f));
    return u;
}

__device__ __forceinline__ void st_tf32x4(uint32_t* p, float4 v) {
    uint4 u;
    u.x = f2tf32(v.x); u.y = f2tf32(v.y);
    u.z = f2tf32(v.z); u.w = f2tf32(v.w);
    *(uint4*)p = u;
}

__device__ __forceinline__ void mma_tf32(float* c, const uint32_t* a,
                                         const uint32_t* b) {
    asm volatile(
        "mma.sync.aligned.m16n8k8.row.col.f32.tf32.tf32.f32 "
        "{%0,%1,%2,%3}, {%4,%5,%6,%7}, {%8,%9}, {%0,%1,%2,%3};\n"
        : "+f"(c[0]), "+f"(c[1]), "+f"(c[2]), "+f"(c[3])
        : "r"(a[0]), "r"(a[1]), "r"(a[2]), "r"(a[3]),
          "r"(b[0]), "r"(b[1]));
}

// ---------------------------------------------------------------------------
// TF32 tensor-core GEMM: Y[M,N] = X[M,K] @ W[N,K]^T
// BM=BN=128, BK=16, 256 threads (8 warps, 2x4), warp tile 64x32 (4x4 atoms
// of m16n8k8). Register double-buffered gmem->smem. Stride-20 smem rows are
// conflict-free for the m16n8k8 fragment access pattern.
// ---------------------------------------------------------------------------
#define GBM 128
#define GBN 128
#define GBK 16
#define GST 20   // smem row stride in words

__global__ __launch_bounds__(256, 2) void gemm_tf32(
    const float* __restrict__ X, const float* __restrict__ W,
    float* __restrict__ Y, int M, int N, int K)
{
    __shared__ __align__(16) uint32_t Xs[GBM * GST];
    __shared__ __align__(16) uint32_t Ws[GBN * GST];

    const int tid  = threadIdx.x;
    const int lane = tid & 31;
    const int warp = tid >> 5;
    const int wm   = warp >> 2;       // 0..1
    const int wn   = warp & 3;        // 0..3
    const int grp  = lane >> 2;       // 0..7
    const int t4   = lane & 3;        // 0..3

    const int row0 = blockIdx.y * GBM;
    const int col0 = blockIdx.x * GBN;

    // Cooperative gmem loads: 2 float4 per thread per operand per k-tile
    const int lr  = tid >> 2;         // 0..63
    const int lc4 = (tid & 3) * 4;    // 0,4,8,12
    const float* Xp0 = X + (size_t)(row0 + lr)      * K + lc4;
    const float* Xp1 = X + (size_t)(row0 + lr + 64) * K + lc4;
    const float* Wp0 = W + (size_t)(col0 + lr)      * K + lc4;
    const float* Wp1 = W + (size_t)(col0 + lr + 64) * K + lc4;

    float acc[4][4][4];
    #pragma unroll
    for (int i = 0; i < 4; i++)
        #pragma unroll
        for (int j = 0; j < 4; j++)
            #pragma unroll
            for (int r = 0; r < 4; r++) acc[i][j][r] = 0.f;

    float4 xv0 = *(const float4*)(Xp0);
    float4 xv1 = *(const float4*)(Xp1);
    float4 wv0 = *(const float4*)(Wp0);
    float4 wv1 = *(const float4*)(Wp1);

    const int niter = K / GBK;   // 64
    for (int it = 0; it < niter; it++) {
        st_tf32x4(Xs + (size_t)lr        * GST + lc4, xv0);
        st_tf32x4(Xs + (size_t)(lr + 64) * GST + lc4, xv1);
        st_tf32x4(Ws + (size_t)lr        * GST + lc4, wv0);
        st_tf32x4(Ws + (size_t)(lr + 64) * GST + lc4, wv1);
        __syncthreads();

        if (it + 1 < niter) {
            const int k0 = (it + 1) * GBK;
            xv0 = *(const float4*)(Xp0 + k0);
            xv1 = *(const float4*)(Xp1 + k0);
            wv0 = *(const float4*)(Wp0 + k0);
            wv1 = *(const float4*)(Wp1 + k0);
        }

        #pragma unroll
        for (int kk = 0; kk < 2; kk++) {
            const int kb = kk * 8;
            uint32_t a[4][4], b[4][2];
            #pragma unroll
            for (int am = 0; am < 4; am++) {
                const int r0 = (wm * 64 + am * 16 + grp) * GST + kb + t4;
                a[am][0] = Xs[r0];
                a[am][1] = Xs[r0 + 8 * GST];
                a[am][2] = Xs[r0 + 4];
                a[am][3] = Xs[r0 + 8 * GST + 4];
            }
            #pragma unroll
            for (int bn = 0; bn < 4; bn++) {
                const int n0 = (wn * 32 + bn * 8 + grp) * GST + kb + t4;
                b[bn][0] = Ws[n0];
                b[bn][1] = Ws[n0 + 4];
            }
            #pragma unroll
            for (int am = 0; am < 4; am++)
                #pragma unroll
                for (int bn = 0; bn < 4; bn++)
                    mma_tf32(acc[am][bn], a[am], b[bn]);
        }
        __syncthreads();
    }

    // Epilogue: c0,c1 -> (row, col..col+1); c2,c3 -> (row+8, ...)
    #pragma unroll
    for (int am = 0; am < 4; am++) {
        const int r = row0 + wm * 64 + am * 16 + grp;
        #pragma unroll
        for (int bn = 0; bn < 4; bn++) {
            const int c = col0 + wn * 32 + bn * 8 + t4 * 2;
            float2 lo = make_float2(acc[am][bn][0], acc[am][bn][1]);
            float2 hi = make_float2(acc[am][bn][2], acc[am][bn][3]);
            *(float2*)(Y + (size_t)r * N + c)       = lo;
            *(float2*)(Y + (size_t)(r + 8) * N + c) = hi;
        }
    }
}

// ---------------------------------------------------------------------------
// Flash attention (causal), fp32. One block per (q-tile=64, head, batch).
// 256 threads, 16x16 grid, 4x4 micro-tiles. PV loop reads P as float4
// (broadcast) to halve smem request count vs scalar reads.
// ---------------------------------------------------------------------------
__global__ __launch_bounds__(256) void attn_fwd(
    const float* __restrict__ Qg, const float* __restrict__ Kg,
    const float* __restrict__ Vg, float* __restrict__ Og)
{
    extern __shared__ __align__(16) float smem[];
    float (*Qs)[68] = (float(*)[68])(smem);              // [d][i]
    float (*Ks)[68] = (float(*)[68])(smem + 1 * 64 * 68);// [d][j]
    float (*Vs)[68] = (float(*)[68])(smem + 2 * 64 * 68);// [j][c]
    float (*Ps)[68] = (float(*)[68])(smem + 3 * 64 * 68);// [i][j]

    const int tid = threadIdx.x;
    const int tx  = tid & 15;          // key / out-col micro
    const int ty  = tid >> 4;          // query-row micro
    const int qt  = blockIdx.x;
    const int q0  = qt * 64;
    const int h   = blockIdx.y;
    const int b   = blockIdx.z;

    const float* Qb = Qg + ((size_t)b * S_LEN + q0) * D_MODEL + h * DH;
    const float* Kb = Kg + (size_t)b * S_LEN * D_MODEL + h * DH;
    const float* Vb = Vg + (size_t)b * S_LEN * D_MODEL + h * DH;

    // Load Q tile transposed (d-major) with the 1/sqrt(DH) scale folded in
    #pragma unroll
    for (int r = 0; r < 4; r++) {
        int idx = tid + r * 256;
        int row = idx >> 4;
        int c4  = (idx & 15) * 4;
        float4 qv = *(const float4*)(Qb + (size_t)row * D_MODEL + c4);
        Qs[c4 + 0][row] = qv.x * 0.125f;
        Qs[c4 + 1][row] = qv.y * 0.125f;
        Qs[c4 + 2][row] = qv.z * 0.125f;
        Qs[c4 + 3][row] = qv.w * 0.125f;
    }

    float m_i[4], l_i[4], o[4][4];
    #pragma unroll
    for (int i = 0; i < 4; i++) {
        m_i[i] = -INFINITY; l_i[i] = 0.f;
        #pragma unroll
        for (int j = 0; j < 4; j++) o[i][j] = 0.f;
    }

    for (int kt = 0; kt <= qt; kt++) {
        const int k0 = kt * 64;
        __syncthreads();

        #pragma unroll
        for (int r = 0; r < 4; r++) {
            int idx = tid + r * 256;
            int row = idx >> 4;
            int c4  = (idx & 15) * 4;
            float4 kv = *(const float4*)(Kb + (size_t)(k0 + row) * D_MODEL + c4);
            Ks[c4 + 0][row] = kv.x; Ks[c4 + 1][row] = kv.y;
            Ks[c4 + 2][row] = kv.z; Ks[c4 + 3][row] = kv.w;
            float4 vv = *(const float4*)(Vb + (size_t)(k0 + row) * D_MODEL + c4);
            *(float4*)&Vs[row][c4] = vv;
        }
        __syncthreads();

        // S = (Q*scale) @ K^T
        float s[4][4] = {};
        #pragma unroll
        for (int d = 0; d < 64; d++) {
            float4 qa = *(const float4*)&Qs[d][ty * 4];
            float4 kb = *(const float4*)&Ks[d][tx * 4];
            float ar[4] = {qa.x, qa.y, qa.z, qa.w};
            float br[4] = {kb.x, kb.y, kb.z, kb.w};
            #pragma unroll
            for (int i = 0; i < 4; i++)
                #pragma unroll
                for (int j = 0; j < 4; j++)
                    s[i][j] = fmaf(ar[i], br[j], s[i][j]);
        }

        if (kt == qt) {
            #pragma unroll
            for (int i = 0; i < 4; i++)
                #pragma unroll
                for (int j = 0; j < 4; j++)
                    if (tx * 4 + j > ty * 4 + i) s[i][j] = -INFINITY;
        }

        // Online softmax update
        #pragma unroll
        for (int i = 0; i < 4; i++) {
            float mloc = fmaxf(fmaxf(s[i][0], s[i][1]), fmaxf(s[i][2], s[i][3]));
            #pragma unroll
            for (int off = 1; off < 16; off <<= 1)
                mloc = fmaxf(mloc, __shfl_xor_sync(0xffffffffu, mloc, off));
            float mnew  = fmaxf(m_i[i], mloc);
            float alpha = __expf(m_i[i] - mnew);
            float psum = 0.f;
            #pragma unroll
            for (int j = 0; j < 4; j++) {
                float p = __expf(s[i][j] - mnew);
                s[i][j] = p;
                psum += p;
            }
            #pragma unroll
            for (int off = 1; off < 16; off <<= 1)
                psum += __shfl_xor_sync(0xffffffffu, psum, off);
            l_i[i] = l_i[i] * alpha + psum;
            m_i[i] = mnew;
            #pragma unroll
            for (int j = 0; j < 4; j++) o[i][j] *= alpha;
            *(float4*)&Ps[ty * 4 + i][tx * 4] =
                make_float4(s[i][0], s[i][1], s[i][2], s[i][3]);
        }
        __syncthreads();

        // O += P @ V  (P read as float4 broadcast, V as float4 rows)
        #pragma unroll
        for (int j0 = 0; j0 < 64; j0 += 4) {
            float4 pv[4];
            #pragma unroll
            for (int i = 0; i < 4; i++)
                pv[i] = *(const float4*)&Ps[ty * 4 + i][j0];
            #pragma unroll
            for (int jj = 0; jj < 4; jj++) {
                float4 vv = *(const float4*)&Vs[j0 + jj][tx * 4];
                #pragma unroll
                for (int i = 0; i < 4; i++) {
                    float p = (jj == 0) ? pv[i].x :
                              (jj == 1) ? pv[i].y :
                              (jj == 2) ? pv[i].z : pv[i].w;
                    o[i][0] = fmaf(p, vv.x, o[i][0]);
                    o[i][1] = fmaf(p, vv.y, o[i][1]);
                    o[i][2] = fmaf(p, vv.z, o[i][2]);
                    o[i][3] = fmaf(p, vv.w, o[i][3]);
                }
            }
        }
    }

    float* Ob = Og + ((size_t)b * S_LEN + q0) * D_MODEL + h * DH;
    #pragma unroll
    for (int i = 0; i < 4; i++) {
        float inv = 1.f / l_i[i];
        float4 ov = make_float4(o[i][0] * inv, o[i][1] * inv,
                                o[i][2] * inv, o[i][3] * inv);
        *(float4*)(Ob + (size_t)(ty * 4 + i) * D_MODEL + tx * 4) = ov;
    }
}

// ---------------------------------------------------------------------------
// Launch
// ---------------------------------------------------------------------------
extern "C" void kernel_launch(void* const* d_in, const int* in_sizes, int n_in,
                              void* d_out, int out_size)
{
    const float* x  = (const float*)d_in[0];
    const float* Wq = (const float*)d_in[1];
    const float* Wk = (const float*)d_in[2];
    const float* Wv = (const float*)d_in[3];
    const float* Wo = (const float*)d_in[4];
    float* out = (float*)d_out;

    float *q, *k, *v, *att;
    cudaGetSymbolAddress((void**)&q,   g_q);
    cudaGetSymbolAddress((void**)&k,   g_k);
    cudaGetSymbolAddress((void**)&v,   g_v);
    cudaGetSymbolAddress((void**)&att, g_att);

    dim3 gg(D_MODEL / GBN, M_ROWS / GBM);   // (8, 32)
    gemm_tf32<<<gg, 256>>>(x, Wq, q, M_ROWS, D_MODEL, D_MODEL);
    gemm_tf32<<<gg, 256>>>(x, Wk, k, M_ROWS, D_MODEL, D_MODEL);
    gemm_tf32<<<gg, 256>>>(x, Wv, v, M_ROWS, D_MODEL, D_MODEL);

    const size_t smem = 4 * 64 * 68 * sizeof(float);  // 69632 B
    cudaFuncSetAttribute(attn_fwd, cudaFuncAttributeMaxDynamicSharedMemorySize,
                         (int)smem);
    attn_fwd<<<dim3(S_LEN / 64, NH, BATCH), 256, smem>>>(q, k, v, att);

    gemm_tf32<<<gg, 256>>>(att, Wo, out, M_ROWS, D_MODEL, D_MODEL);
}

// round 4
// speedup vs baseline: 2.9334x; 1.7588x over previous
#include <cuda_runtime.h>
#include <math.h>
#include <stdint.h>

#define S_LEN   2048
#define D_MODEL 1024
#define NH      16
#define DH      64
#define BATCH   2
#define M_ROWS  (BATCH * S_LEN)   // 4096

// ---------------------------------------------------------------------------
// Scratch (device globals: allocation-free, graph-capture safe)
// ---------------------------------------------------------------------------
__device__ float g_q[M_ROWS * D_MODEL];
__device__ float g_k[M_ROWS * D_MODEL];
__device__ float g_v[M_ROWS * D_MODEL];
__device__ float g_att[M_ROWS * D_MODEL];

// ---------------------------------------------------------------------------
// tf32 helpers
// ---------------------------------------------------------------------------
__device__ __forceinline__ uint32_t f2tf32(float f) {
    uint32_t u;
    asm("cvt.rna.tf32.f32 %0, %1;" : "=r"(u) : "f"(f));
    return u;
}

__device__ __forceinline__ void st_tf32x4(uint32_t* p, float4 v) {
    uint4 u;
    u.x = f2tf32(v.x); u.y = f2tf32(v.y);
    u.z = f2tf32(v.z); u.w = f2tf32(v.w);
    *(uint4*)p = u;
}

__device__ __forceinline__ void mma_tf32(float* c, const uint32_t* a,
                                         const uint32_t* b) {
    asm volatile(
        "mma.sync.aligned.m16n8k8.row.col.f32.tf32.tf32.f32 "
        "{%0,%1,%2,%3}, {%4,%5,%6,%7}, {%8,%9}, {%0,%1,%2,%3};\n"
        : "+f"(c[0]), "+f"(c[1]), "+f"(c[2]), "+f"(c[3])
        : "r"(a[0]), "r"(a[1]), "r"(a[2]), "r"(a[3]),
          "r"(b[0]), "r"(b[1]));
}

// ---------------------------------------------------------------------------
// TF32 tensor-core GEMM: Y[M,N] = X[M,K] @ W[N,K]^T   (unchanged from R2)
// ---------------------------------------------------------------------------
#define GBM 128
#define GBN 128
#define GBK 16
#define GST 20

__global__ __launch_bounds__(256, 2) void gemm_tf32(
    const float* __restrict__ X, const float* __restrict__ W,
    float* __restrict__ Y, int M, int N, int K)
{
    __shared__ __align__(16) uint32_t Xs[GBM * GST];
    __shared__ __align__(16) uint32_t Ws[GBN * GST];

    const int tid  = threadIdx.x;
    const int lane = tid & 31;
    const int warp = tid >> 5;
    const int wm   = warp >> 2;
    const int wn   = warp & 3;
    const int grp  = lane >> 2;
    const int t4   = lane & 3;

    const int row0 = blockIdx.y * GBM;
    const int col0 = blockIdx.x * GBN;

    const int lr  = tid >> 2;
    const int lc4 = (tid & 3) * 4;
    const float* Xp0 = X + (size_t)(row0 + lr)      * K + lc4;
    const float* Xp1 = X + (size_t)(row0 + lr + 64) * K + lc4;
    const float* Wp0 = W + (size_t)(col0 + lr)      * K + lc4;
    const float* Wp1 = W + (size_t)(col0 + lr + 64) * K + lc4;

    float acc[4][4][4];
    #pragma unroll
    for (int i = 0; i < 4; i++)
        #pragma unroll
        for (int j = 0; j < 4; j++)
            #pragma unroll
            for (int r = 0; r < 4; r++) acc[i][j][r] = 0.f;

    float4 xv0 = *(const float4*)(Xp0);
    float4 xv1 = *(const float4*)(Xp1);
    float4 wv0 = *(const float4*)(Wp0);
    float4 wv1 = *(const float4*)(Wp1);

    const int niter = K / GBK;
    for (int it = 0; it < niter; it++) {
        st_tf32x4(Xs + (size_t)lr        * GST + lc4, xv0);
        st_tf32x4(Xs + (size_t)(lr + 64) * GST + lc4, xv1);
        st_tf32x4(Ws + (size_t)lr        * GST + lc4, wv0);
        st_tf32x4(Ws + (size_t)(lr + 64) * GST + lc4, wv1);
        __syncthreads();

        if (it + 1 < niter) {
            const int k0 = (it + 1) * GBK;
            xv0 = *(const float4*)(Xp0 + k0);
            xv1 = *(const float4*)(Xp1 + k0);
            wv0 = *(const float4*)(Wp0 + k0);
            wv1 = *(const float4*)(Wp1 + k0);
        }

        #pragma unroll
        for (int kk = 0; kk < 2; kk++) {
            const int kb = kk * 8;
            uint32_t a[4][4], b[4][2];
            #pragma unroll
            for (int am = 0; am < 4; am++) {
                const int r0 = (wm * 64 + am * 16 + grp) * GST + kb + t4;
                a[am][0] = Xs[r0];
                a[am][1] = Xs[r0 + 8 * GST];
                a[am][2] = Xs[r0 + 4];
                a[am][3] = Xs[r0 + 8 * GST + 4];
            }
            #pragma unroll
            for (int bn = 0; bn < 4; bn++) {
                const int n0 = (wn * 32 + bn * 8 + grp) * GST + kb + t4;
                b[bn][0] = Ws[n0];
                b[bn][1] = Ws[n0 + 4];
            }
            #pragma unroll
            for (int am = 0; am < 4; am++)
                #pragma unroll
                for (int bn = 0; bn < 4; bn++)
                    mma_tf32(acc[am][bn], a[am], b[bn]);
        }
        __syncthreads();
    }

    #pragma unroll
    for (int am = 0; am < 4; am++) {
        const int r = row0 + wm * 64 + am * 16 + grp;
        #pragma unroll
        for (int bn = 0; bn < 4; bn++) {
            const int c = col0 + wn * 32 + bn * 8 + t4 * 2;
            float2 lo = make_float2(acc[am][bn][0], acc[am][bn][1]);
            float2 hi = make_float2(acc[am][bn][2], acc[am][bn][3]);
            *(float2*)(Y + (size_t)r * N + c)       = lo;
            *(float2*)(Y + (size_t)(r + 8) * N + c) = hi;
        }
    }
}

// ---------------------------------------------------------------------------
// Tensor-core flash attention (causal), tf32 mma, fp32 softmax.
// BQ=64, BKV=64, 128 threads (4 warps). Warp w owns q-rows [16w, 16w+16).
// Each thread holds 2 rows (grp, grp+8) x 16 cols of S and of O as mma
// accumulator fragments. P goes through smem in tf32 for the PV mma.
// All fragment LDS patterns are bank-conflict-free by stride choice.
// ---------------------------------------------------------------------------
#define AST 68   // word stride for Qs/Ks/Ps (4*grp+t4 bank pattern)
#define VST 72   // word stride for Vs      (8*t4+grp bank pattern)

__global__ __launch_bounds__(128) void attn_tc(
    const float* __restrict__ Qg, const float* __restrict__ Kg,
    const float* __restrict__ Vg, float* __restrict__ Og)
{
    extern __shared__ __align__(16) uint32_t sm[];
    uint32_t* Qs = sm;                 // [64][AST]  (i, d)  scaled tf32
    uint32_t* Ks = Qs + 64 * AST;      // [64][AST]  (j, d)
    uint32_t* Ps = Ks + 64 * AST;      // [64][AST]  (i, j)
    uint32_t* Vs = Ps + 64 * AST;      // [64][VST]  (j, c)

    const int tid  = threadIdx.x;
    const int lane = tid & 31;
    const int warp = tid >> 5;
    const int grp  = lane >> 2;        // 0..7
    const int t4   = lane & 3;         // 0..3
    const int m0   = warp * 16;

    const int qt = blockIdx.x;
    const int q0 = qt * 64;
    const int h  = blockIdx.y;
    const int b  = blockIdx.z;

    const float* Qb = Qg + ((size_t)b * S_LEN + q0) * D_MODEL + h * DH;
    const float* Kb = Kg + (size_t)b * S_LEN * D_MODEL + h * DH;
    const float* Vb = Vg + (size_t)b * S_LEN * D_MODEL + h * DH;

    // Load Q tile once, scale folded, tf32 in smem
    #pragma unroll
    for (int r = 0; r < 8; r++) {
        int idx = tid + r * 128;
        int row = idx >> 4;
        int c4  = (idx & 15) * 4;
        float4 qv = *(const float4*)(Qb + (size_t)row * D_MODEL + c4);
        qv.x *= 0.125f; qv.y *= 0.125f; qv.z *= 0.125f; qv.w *= 0.125f;
        st_tf32x4(Qs + row * AST + c4, qv);
    }

    float mr[2] = {-INFINITY, -INFINITY};
    float lr_[2] = {0.f, 0.f};
    float o[8][4];
    #pragma unroll
    for (int n = 0; n < 8; n++)
        #pragma unroll
        for (int r = 0; r < 4; r++) o[n][r] = 0.f;

    for (int kt = 0; kt <= qt; kt++) {
        const int k0 = kt * 64;
        __syncthreads();   // protect Ks/Vs against previous iter's mma reads

        #pragma unroll
        for (int r = 0; r < 8; r++) {
            int idx = tid + r * 128;
            int row = idx >> 4;
            int c4  = (idx & 15) * 4;
            float4 kv = *(const float4*)(Kb + (size_t)(k0 + row) * D_MODEL + c4);
            st_tf32x4(Ks + row * AST + c4, kv);
            float4 vv = *(const float4*)(Vb + (size_t)(k0 + row) * D_MODEL + c4);
            st_tf32x4(Vs + row * VST + c4, vv);
        }
        __syncthreads();

        // ---- S = Q K^T via tf32 mma ----
        float s[8][4];
        #pragma unroll
        for (int n = 0; n < 8; n++)
            #pragma unroll
            for (int r = 0; r < 4; r++) s[n][r] = 0.f;

        #pragma unroll
        for (int kb = 0; kb < 8; kb++) {
            const int kw = kb * 8;
            uint32_t a[4];
            a[0] = Qs[(m0 + grp)     * AST + kw + t4];
            a[1] = Qs[(m0 + grp + 8) * AST + kw + t4];
            a[2] = Qs[(m0 + grp)     * AST + kw + t4 + 4];
            a[3] = Qs[(m0 + grp + 8) * AST + kw + t4 + 4];
            #pragma unroll
            for (int n = 0; n < 8; n++) {
                uint32_t bf[2];
                bf[0] = Ks[(n * 8 + grp) * AST + kw + t4];
                bf[1] = Ks[(n * 8 + grp) * AST + kw + t4 + 4];
                mma_tf32(s[n], a, bf);
            }
        }

        // ---- causal mask (diagonal tile only) ----
        if (kt == qt) {
            const int i0 = m0 + grp, i1 = i0 + 8;
            #pragma unroll
            for (int n = 0; n < 8; n++) {
                const int j0 = n * 8 + t4 * 2;
                if (j0     > i0) s[n][0] = -INFINITY;
                if (j0 + 1 > i0) s[n][1] = -INFINITY;
                if (j0     > i1) s[n][2] = -INFINITY;
                if (j0 + 1 > i1) s[n][3] = -INFINITY;
            }
        }

        // ---- online softmax (rows grp, grp+8; quad = lanes xor 1,2) ----
        float ml0 = -INFINITY, ml1 = -INFINITY;
        #pragma unroll
        for (int n = 0; n < 8; n++) {
            ml0 = fmaxf(ml0, fmaxf(s[n][0], s[n][1]));
            ml1 = fmaxf(ml1, fmaxf(s[n][2], s[n][3]));
        }
        ml0 = fmaxf(ml0, __shfl_xor_sync(0xffffffffu, ml0, 1));
        ml0 = fmaxf(ml0, __shfl_xor_sync(0xffffffffu, ml0, 2));
        ml1 = fmaxf(ml1, __shfl_xor_sync(0xffffffffu, ml1, 1));
        ml1 = fmaxf(ml1, __shfl_xor_sync(0xffffffffu, ml1, 2));

        const float mn0 = fmaxf(mr[0], ml0);
        const float mn1 = fmaxf(mr[1], ml1);
        const float al0 = __expf(mr[0] - mn0);
        const float al1 = __expf(mr[1] - mn1);
        mr[0] = mn0; mr[1] = mn1;

        float ps0 = 0.f, ps1 = 0.f;
        #pragma unroll
        for (int n = 0; n < 8; n++) {
            s[n][0] = __expf(s[n][0] - mn0);
            s[n][1] = __expf(s[n][1] - mn0);
            s[n][2] = __expf(s[n][2] - mn1);
            s[n][3] = __expf(s[n][3] - mn1);
            ps0 += s[n][0] + s[n][1];
            ps1 += s[n][2] + s[n][3];
        }
        ps0 += __shfl_xor_sync(0xffffffffu, ps0, 1);
        ps0 += __shfl_xor_sync(0xffffffffu, ps0, 2);
        ps1 += __shfl_xor_sync(0xffffffffu, ps1, 1);
        ps1 += __shfl_xor_sync(0xffffffffu, ps1, 2);
        lr_[0] = lr_[0] * al0 + ps0;
        lr_[1] = lr_[1] * al1 + ps1;

        #pragma unroll
        for (int n = 0; n < 8; n++) {
            o[n][0] *= al0; o[n][1] *= al0;
            o[n][2] *= al1; o[n][3] *= al1;
        }

        // ---- P -> smem (tf32), warp-private rows ----
        #pragma unroll
        for (int n = 0; n < 8; n++) {
            uint2 p0 = make_uint2(f2tf32(s[n][0]), f2tf32(s[n][1]));
            uint2 p1 = make_uint2(f2tf32(s[n][2]), f2tf32(s[n][3]));
            *(uint2*)(Ps + (m0 + grp)     * AST + n * 8 + t4 * 2) = p0;
            *(uint2*)(Ps + (m0 + grp + 8) * AST + n * 8 + t4 * 2) = p1;
        }
        __syncwarp();

        // ---- O += P V via tf32 mma ----
        #pragma unroll
        for (int kb = 0; kb < 8; kb++) {
            const int jw = kb * 8;
            uint32_t a[4];
            a[0] = Ps[(m0 + grp)     * AST + jw + t4];
            a[1] = Ps[(m0 + grp + 8) * AST + jw + t4];
            a[2] = Ps[(m0 + grp)     * AST + jw + t4 + 4];
            a[3] = Ps[(m0 + grp + 8) * AST + jw + t4 + 4];
            #pragma unroll
            for (int n = 0; n < 8; n++) {
                uint32_t bf[2];
                bf[0] = Vs[(jw + t4)     * VST + n * 8 + grp];
                bf[1] = Vs[(jw + t4 + 4) * VST + n * 8 + grp];
                mma_tf32(o[n], a, bf);
            }
        }
    }

    // ---- normalize + store ----
    const float inv0 = 1.f / lr_[0];
    const float inv1 = 1.f / lr_[1];
    float* Ob = Og + ((size_t)b * S_LEN + q0 + m0) * D_MODEL + h * DH;
    #pragma unroll
    for (int n = 0; n < 8; n++) {
        const int c = n * 8 + t4 * 2;
        *(float2*)(Ob + (size_t)grp * D_MODEL + c) =
            make_float2(o[n][0] * inv0, o[n][1] * inv0);
        *(float2*)(Ob + (size_t)(grp + 8) * D_MODEL + c) =
            make_float2(o[n][2] * inv1, o[n][3] * inv1);
    }
}

// ---------------------------------------------------------------------------
// Launch
// ---------------------------------------------------------------------------
extern "C" void kernel_launch(void* const* d_in, const int* in_sizes, int n_in,
                              void* d_out, int out_size)
{
    const float* x  = (const float*)d_in[0];
    const float* Wq = (const float*)d_in[1];
    const float* Wk = (const float*)d_in[2];
    const float* Wv = (const float*)d_in[3];
    const float* Wo = (const float*)d_in[4];
    float* out = (float*)d_out;

    float *q, *k, *v, *att;
    cudaGetSymbolAddress((void**)&q,   g_q);
    cudaGetSymbolAddress((void**)&k,   g_k);
    cudaGetSymbolAddress((void**)&v,   g_v);
    cudaGetSymbolAddress((void**)&att, g_att);

    dim3 gg(D_MODEL / GBN, M_ROWS / GBM);   // (8, 32)
    gemm_tf32<<<gg, 256>>>(x, Wq, q, M_ROWS, D_MODEL, D_MODEL);
    gemm_tf32<<<gg, 256>>>(x, Wk, k, M_ROWS, D_MODEL, D_MODEL);
    gemm_tf32<<<gg, 256>>>(x, Wv, v, M_ROWS, D_MODEL, D_MODEL);

    const int smem = (3 * 64 * AST + 64 * VST) * 4;   // 70656 B
    cudaFuncSetAttribute(attn_tc, cudaFuncAttributeMaxDynamicSharedMemorySize,
                         smem);
    attn_tc<<<dim3(S_LEN / 64, NH, BATCH), 128, smem>>>(q, k, v, att);

    gemm_tf32<<<gg, 256>>>(att, Wo, out, M_ROWS, D_MODEL, D_MODEL);
}

// round 5
// speedup vs baseline: 3.4445x; 1.1742x over previous
#include <cuda_runtime.h>
#include <math.h>
#include <stdint.h>

#define S_LEN   2048
#define D_MODEL 1024
#define NH      16
#define DH      64
#define BATCH   2
#define M_ROWS  (BATCH * S_LEN)   // 4096

// ---------------------------------------------------------------------------
// Scratch (device globals: allocation-free, graph-capture safe)
// ---------------------------------------------------------------------------
__device__ float g_q[M_ROWS * D_MODEL];
__device__ float g_k[M_ROWS * D_MODEL];
__device__ float g_v[M_ROWS * D_MODEL];
__device__ float g_att[M_ROWS * D_MODEL];

// ---------------------------------------------------------------------------
// Helpers
// ---------------------------------------------------------------------------
__device__ __forceinline__ uint32_t f2tf32(float f) {
    uint32_t u;
    asm("cvt.rna.tf32.f32 %0, %1;" : "=r"(u) : "f"(f));
    return u;
}

__device__ __forceinline__ void st_tf32x4(uint32_t* p, float4 v) {
    uint4 u;
    u.x = f2tf32(v.x); u.y = f2tf32(v.y);
    u.z = f2tf32(v.z); u.w = f2tf32(v.w);
    *(uint4*)p = u;
}

// LDS raw fp32 bits + round-to-nearest tf32 (identical value to cvt-before-STS)
__device__ __forceinline__ uint32_t lds_tf32(const uint32_t* p) {
    return f2tf32(__uint_as_float(*p));
}

__device__ __forceinline__ void mma_tf32(float* c, const uint32_t* a,
                                         const uint32_t* b) {
    asm volatile(
        "mma.sync.aligned.m16n8k8.row.col.f32.tf32.tf32.f32 "
        "{%0,%1,%2,%3}, {%4,%5,%6,%7}, {%8,%9}, {%0,%1,%2,%3};\n"
        : "+f"(c[0]), "+f"(c[1]), "+f"(c[2]), "+f"(c[3])
        : "r"(a[0]), "r"(a[1]), "r"(a[2]), "r"(a[3]),
          "r"(b[0]), "r"(b[1]));
}

__device__ __forceinline__ uint32_t smem_u32(const void* p) {
    return (uint32_t)__cvta_generic_to_shared(p);
}

#define CP_ASYNC16(dst, src) \
    asm volatile("cp.async.cg.shared.global [%0], [%1], 16;\n" \
                 :: "r"(dst), "l"(src))
#define CP_COMMIT() asm volatile("cp.async.commit_group;\n" ::: "memory")

// ---------------------------------------------------------------------------
// TF32 tensor-core GEMM, cp.async double-buffered: Y[M,N] = X @ W^T.
// BM=BN=128, BK=32, 256 threads (8 warps, 2x4), warp tile 64x32.
// gridDim.z selects among 3 (W, Y) pairs so QKV runs as one launch.
// ---------------------------------------------------------------------------
#define GBM 128
#define GBN 128
#define GBK 32
#define KST 36                       // smem row stride in words
#define GSTAGE_W (128 * KST)         // words per operand per stage
#define GSMEM_BYTES (4 * GSTAGE_W * 4)   // 2 stages x 2 operands = 73728 B

__global__ __launch_bounds__(256, 2) void gemm_tc(
    const float* __restrict__ X,
    const float* __restrict__ W0, const float* __restrict__ W1,
    const float* __restrict__ W2,
    float* __restrict__ Y0, float* __restrict__ Y1, float* __restrict__ Y2,
    int M, int N, int K)
{
    extern __shared__ __align__(16) uint32_t gsm[];

    const int z = blockIdx.z;
    const float* W = (z == 0) ? W0 : (z == 1) ? W1 : W2;
    float*       Y = (z == 0) ? Y0 : (z == 1) ? Y1 : Y2;

    const int tid  = threadIdx.x;
    const int lane = tid & 31;
    const int warp = tid >> 5;
    const int wm   = warp >> 2;       // 0..1
    const int wn   = warp & 3;        // 0..3
    const int grp  = lane >> 2;       // 0..7
    const int t4   = lane & 3;        // 0..3

    const int row0 = blockIdx.y * GBM;
    const int col0 = blockIdx.x * GBN;

    // cp.async source/dest mapping: 4 rows per thread per operand per stage
    const int lr  = tid >> 3;         // 0..31
    const int lc4 = (tid & 7) * 4;    // 0..28
    const float* Xg = X + (size_t)(row0 + lr) * K + lc4;
    const float* Wg = W + (size_t)(col0 + lr) * K + lc4;
    const uint32_t sbase = smem_u32(gsm);

    auto issue_stage = [&](int it, int s) {
        const int k0 = it * GBK;
        uint32_t xd = sbase + (uint32_t)((s * 2)     * GSTAGE_W + lr * KST + lc4) * 4u;
        uint32_t wd = sbase + (uint32_t)((s * 2 + 1) * GSTAGE_W + lr * KST + lc4) * 4u;
        #pragma unroll
        for (int i = 0; i < 4; i++) {
            CP_ASYNC16(xd + (uint32_t)(i * 32 * KST * 4), Xg + k0 + (size_t)i * 32 * K);
            CP_ASYNC16(wd + (uint32_t)(i * 32 * KST * 4), Wg + k0 + (size_t)i * 32 * K);
        }
        CP_COMMIT();
    };

    float acc[4][4][4] = {};

    const int niter = K / GBK;        // 32
    issue_stage(0, 0);
    issue_stage(1, 1);

    for (int it = 0; it < niter; it++) {
        if (it + 1 < niter)
            asm volatile("cp.async.wait_group 1;\n" ::: "memory");
        else
            asm volatile("cp.async.wait_group 0;\n" ::: "memory");
        __syncthreads();

        const uint32_t* Xs = gsm + (size_t)((it & 1) * 2) * GSTAGE_W;
        const uint32_t* Ws = Xs + GSTAGE_W;

        #pragma unroll
        for (int kk = 0; kk < 4; kk++) {
            const int kb = kk * 8;
            uint32_t a[4][4], b[4][2];
            #pragma unroll
            for (int am = 0; am < 4; am++) {
                const uint32_t* p = Xs + (wm * 64 + am * 16 + grp) * KST + kb + t4;
                a[am][0] = lds_tf32(p);
                a[am][1] = lds_tf32(p + 8 * KST);
                a[am][2] = lds_tf32(p + 4);
                a[am][3] = lds_tf32(p + 8 * KST + 4);
            }
            #pragma unroll
            for (int bn = 0; bn < 4; bn++) {
                const uint32_t* p = Ws + (wn * 32 + bn * 8 + grp) * KST + kb + t4;
                b[bn][0] = lds_tf32(p);
                b[bn][1] = lds_tf32(p + 4);
            }
            #pragma unroll
            for (int am = 0; am < 4; am++)
                #pragma unroll
                for (int bn = 0; bn < 4; bn++)
                    mma_tf32(acc[am][bn], a[am], b[bn]);
        }
        __syncthreads();
        if (it + 2 < niter) issue_stage(it + 2, it & 1);
    }

    #pragma unroll
    for (int am = 0; am < 4; am++) {
        const int r = row0 + wm * 64 + am * 16 + grp;
        #pragma unroll
        for (int bn = 0; bn < 4; bn++) {
            const int c = col0 + wn * 32 + bn * 8 + t4 * 2;
            *(float2*)(Y + (size_t)r * N + c) =
                make_float2(acc[am][bn][0], acc[am][bn][1]);
            *(float2*)(Y + (size_t)(r + 8) * N + c) =
                make_float2(acc[am][bn][2], acc[am][bn][3]);
        }
    }
}

// ---------------------------------------------------------------------------
// Tensor-core flash attention (causal), tf32 mma, fp32 softmax.
// BQ=128, BKV=64, 256 threads (8 warps). Warp w owns q-rows [16w, 16w+16).
// Heavy q-tiles scheduled first; fully-masked warp-tiles skipped.
// ---------------------------------------------------------------------------
#define AST 68   // word stride for Qs/Ks/Ps
#define VST 72   // word stride for Vs
#define ATTN_SMEM_BYTES ((128 * AST + 64 * AST + 128 * AST + 64 * VST) * 4)

__global__ __launch_bounds__(256, 2) void attn_tc(
    const float* __restrict__ Qg, const float* __restrict__ Kg,
    const float* __restrict__ Vg, float* __restrict__ Og)
{
    extern __shared__ __align__(16) uint32_t sm[];
    uint32_t* Qs = sm;                  // [128][AST] (i, d) scaled tf32
    uint32_t* Ks = Qs + 128 * AST;      // [64][AST]  (j, d)
    uint32_t* Ps = Ks + 64 * AST;       // [128][AST] (i, j)
    uint32_t* Vs = Ps + 128 * AST;      // [64][VST]  (j, c)

    const int tid  = threadIdx.x;
    const int lane = tid & 31;
    const int warp = tid >> 5;
    const int grp  = lane >> 2;         // 0..7
    const int t4   = lane & 3;          // 0..3
    const int m0   = warp * 16;

    const int qt = (gridDim.x - 1) - blockIdx.x;   // heavy tiles first
    const int q0 = qt * 128;
    const int h  = blockIdx.y;
    const int b  = blockIdx.z;

    const float* Qb = Qg + ((size_t)b * S_LEN + q0) * D_MODEL + h * DH;
    const float* Kb = Kg + (size_t)b * S_LEN * D_MODEL + h * DH;
    const float* Vb = Vg + (size_t)b * S_LEN * D_MODEL + h * DH;

    // Load Q tile once (128 rows), scale folded, tf32 in smem
    #pragma unroll
    for (int r = 0; r < 8; r++) {
        int idx = tid + r * 256;
        int row = idx >> 4;               // 0..127
        int c4  = (idx & 15) * 4;         // 0..60
        float4 qv = *(const float4*)(Qb + (size_t)row * D_MODEL + c4);
        qv.x *= 0.125f; qv.y *= 0.125f; qv.z *= 0.125f; qv.w *= 0.125f;
        st_tf32x4(Qs + row * AST + c4, qv);
    }

    float mr[2]  = {-INFINITY, -INFINITY};
    float lr_[2] = {0.f, 0.f};
    float o[8][4];
    #pragma unroll
    for (int n = 0; n < 8; n++)
        #pragma unroll
        for (int r = 0; r < 4; r++) o[n][r] = 0.f;

    const int ntiles = 2 * qt + 2;
    for (int kt = 0; kt < ntiles; kt++) {
        const int k0 = kt * 64;
        __syncthreads();   // protect Ks/Vs against previous iter's mma reads

        #pragma unroll
        for (int r = 0; r < 4; r++) {
            int idx = tid + r * 256;
            int row = idx >> 4;           // 0..63
            int c4  = (idx & 15) * 4;
            float4 kv = *(const float4*)(Kb + (size_t)(k0 + row) * D_MODEL + c4);
            st_tf32x4(Ks + row * AST + c4, kv);
            float4 vv = *(const float4*)(Vb + (size_t)(k0 + row) * D_MODEL + c4);
            st_tf32x4(Vs + row * VST + c4, vv);
        }
        __syncthreads();

        // Fully masked for this warp's 16 rows? (j_min = k0 > i_max)
        const bool active = (k0 <= q0 + m0 + 15);
        if (active) {
            // ---- S = Q K^T via tf32 mma ----
            float s[8][4];
            #pragma unroll
            for (int n = 0; n < 8; n++)
                #pragma unroll
                for (int r = 0; r < 4; r++) s[n][r] = 0.f;

            #pragma unroll
            for (int kb = 0; kb < 8; kb++) {
                const int kw = kb * 8;
                uint32_t a[4];
                a[0] = Qs[(m0 + grp)     * AST + kw + t4];
                a[1] = Qs[(m0 + grp + 8) * AST + kw + t4];
                a[2] = Qs[(m0 + grp)     * AST + kw + t4 + 4];
                a[3] = Qs[(m0 + grp + 8) * AST + kw + t4 + 4];
                #pragma unroll
                for (int n = 0; n < 8; n++) {
                    uint32_t bf[2];
                    bf[0] = Ks[(n * 8 + grp) * AST + kw + t4];
                    bf[1] = Ks[(n * 8 + grp) * AST + kw + t4 + 4];
                    mma_tf32(s[n], a, bf);
                }
            }

            // ---- causal mask (only when the tile clips this warp's rows) ----
            if (k0 + 63 > q0 + m0) {
                const int i0 = q0 + m0 + grp, i1 = i0 + 8;
                #pragma unroll
                for (int n = 0; n < 8; n++) {
                    const int j0 = k0 + n * 8 + t4 * 2;
                    if (j0     > i0) s[n][0] = -INFINITY;
                    if (j0 + 1 > i0) s[n][1] = -INFINITY;
                    if (j0     > i1) s[n][2] = -INFINITY;
                    if (j0 + 1 > i1) s[n][3] = -INFINITY;
                }
            }

            // ---- online softmax (rows grp, grp+8; quad shuffles) ----
            float ml0 = -INFINITY, ml1 = -INFINITY;
            #pragma unroll
            for (int n = 0; n < 8; n++) {
                ml0 = fmaxf(ml0, fmaxf(s[n][0], s[n][1]));
                ml1 = fmaxf(ml1, fmaxf(s[n][2], s[n][3]));
            }
            ml0 = fmaxf(ml0, __shfl_xor_sync(0xffffffffu, ml0, 1));
            ml0 = fmaxf(ml0, __shfl_xor_sync(0xffffffffu, ml0, 2));
            ml1 = fmaxf(ml1, __shfl_xor_sync(0xffffffffu, ml1, 1));
            ml1 = fmaxf(ml1, __shfl_xor_sync(0xffffffffu, ml1, 2));

            const float mn0 = fmaxf(mr[0], ml0);
            const float mn1 = fmaxf(mr[1], ml1);
            const float al0 = __expf(mr[0] - mn0);
            const float al1 = __expf(mr[1] - mn1);
            mr[0] = mn0; mr[1] = mn1;

            float ps0 = 0.f, ps1 = 0.f;
            #pragma unroll
            for (int n = 0; n < 8; n++) {
                s[n][0] = __expf(s[n][0] - mn0);
                s[n][1] = __expf(s[n][1] - mn0);
                s[n][2] = __expf(s[n][2] - mn1);
                s[n][3] = __expf(s[n][3] - mn1);
                ps0 += s[n][0] + s[n][1];
                ps1 += s[n][2] + s[n][3];
            }
            ps0 += __shfl_xor_sync(0xffffffffu, ps0, 1);
            ps0 += __shfl_xor_sync(0xffffffffu, ps0, 2);
            ps1 += __shfl_xor_sync(0xffffffffu, ps1, 1);
            ps1 += __shfl_xor_sync(0xffffffffu, ps1, 2);
            lr_[0] = lr_[0] * al0 + ps0;
            lr_[1] = lr_[1] * al1 + ps1;

            #pragma unroll
            for (int n = 0; n < 8; n++) {
                o[n][0] *= al0; o[n][1] *= al0;
                o[n][2] *= al1; o[n][3] *= al1;
            }

            // ---- P -> smem (tf32), warp-private rows ----
            #pragma unroll
            for (int n = 0; n < 8; n++) {
                *(uint2*)(Ps + (m0 + grp)     * AST + n * 8 + t4 * 2) =
                    make_uint2(f2tf32(s[n][0]), f2tf32(s[n][1]));
                *(uint2*)(Ps + (m0 + grp + 8) * AST + n * 8 + t4 * 2) =
                    make_uint2(f2tf32(s[n][2]), f2tf32(s[n][3]));
            }
            __syncwarp();

            // ---- O += P V via tf32 mma ----
            #pragma unroll
            for (int kb = 0; kb < 8; kb++) {
                const int jw = kb * 8;
                uint32_t a[4];
                a[0] = Ps[(m0 + grp)     * AST + jw + t4];
                a[1] = Ps[(m0 + grp + 8) * AST + jw + t4];
                a[2] = Ps[(m0 + grp)     * AST + jw + t4 + 4];
                a[3] = Ps[(m0 + grp + 8) * AST + jw + t4 + 4];
                #pragma unroll
                for (int n = 0; n < 8; n++) {
                    uint32_t bf[2];
                    bf[0] = Vs[(jw + t4)     * VST + n * 8 + grp];
                    bf[1] = Vs[(jw + t4 + 4) * VST + n * 8 + grp];
                    mma_tf32(o[n], a, bf);
                }
            }
        }
    }

    // ---- normalize + store ----
    const float inv0 = 1.f / lr_[0];
    const float inv1 = 1.f / lr_[1];
    float* Ob = Og + ((size_t)b * S_LEN + q0 + m0) * D_MODEL + h * DH;
    #pragma unroll
    for (int n = 0; n < 8; n++) {
        const int c = n * 8 + t4 * 2;
        *(float2*)(Ob + (size_t)grp * D_MODEL + c) =
            make_float2(o[n][0] * inv0, o[n][1] * inv0);
        *(float2*)(Ob + (size_t)(grp + 8) * D_MODEL + c) =
            make_float2(o[n][2] * inv1, o[n][3] * inv1);
    }
}

// ---------------------------------------------------------------------------
// Launch
// ---------------------------------------------------------------------------
extern "C" void kernel_launch(void* const* d_in, const int* in_sizes, int n_in,
                              void* d_out, int out_size)
{
    const float* x  = (const float*)d_in[0];
    const float* Wq = (const float*)d_in[1];
    const float* Wk = (const float*)d_in[2];
    const float* Wv = (const float*)d_in[3];
    const float* Wo = (const float*)d_in[4];
    float* out = (float*)d_out;

    float *q, *k, *v, *att;
    cudaGetSymbolAddress((void**)&q,   g_q);
    cudaGetSymbolAddress((void**)&k,   g_k);
    cudaGetSymbolAddress((void**)&v,   g_v);
    cudaGetSymbolAddress((void**)&att, g_att);

    cudaFuncSetAttribute(gemm_tc, cudaFuncAttributeMaxDynamicSharedMemorySize,
                         GSMEM_BYTES);
    cudaFuncSetAttribute(attn_tc, cudaFuncAttributeMaxDynamicSharedMemorySize,
                         ATTN_SMEM_BYTES);

    // Fused QKV projections: one launch, z selects W/Y
    dim3 gq(D_MODEL / GBN, M_ROWS / GBM, 3);   // (8, 32, 3)
    gemm_tc<<<gq, 256, GSMEM_BYTES>>>(x, Wq, Wk, Wv, q, k, v,
                                      M_ROWS, D_MODEL, D_MODEL);

    attn_tc<<<dim3(S_LEN / 128, NH, BATCH), 256, ATTN_SMEM_BYTES>>>(q, k, v, att);

    dim3 go(D_MODEL / GBN, M_ROWS / GBM, 1);
    gemm_tc<<<go, 256, GSMEM_BYTES>>>(att, Wo, Wo, Wo, out, out, out,
                                      M_ROWS, D_MODEL, D_MODEL);
}

// round 8
// speedup vs baseline: 4.8629x; 1.4118x over previous
#include <cuda_runtime.h>
#include <cuda_fp16.h>
#include <math.h>
#include <stdint.h>

#define S_LEN   2048
#define D_MODEL 1024
#define NH      16
#define DH      64
#define BATCH   2
#define M_ROWS  (BATCH * S_LEN)   // 4096

// ---------------------------------------------------------------------------
// Scratch (device globals: allocation-free, graph-capture safe)
// ---------------------------------------------------------------------------
__device__ __half g_qh[M_ROWS * D_MODEL];
__device__ __half g_kh[M_ROWS * D_MODEL];
__device__ __half g_vh[M_ROWS * D_MODEL];
__device__ __half g_atth[M_ROWS * D_MODEL];
__device__ __half g_xh[M_ROWS * D_MODEL];
__device__ __half g_wh[4][D_MODEL * D_MODEL];

// ---------------------------------------------------------------------------
// Helpers
// ---------------------------------------------------------------------------
__device__ __forceinline__ void mma_f16(float* c, const uint32_t* a,
                                        const uint32_t* b) {
    asm volatile(
        "mma.sync.aligned.m16n8k16.row.col.f32.f16.f16.f32 "
        "{%0,%1,%2,%3}, {%4,%5,%6,%7}, {%8,%9}, {%0,%1,%2,%3};\n"
        : "+f"(c[0]), "+f"(c[1]), "+f"(c[2]), "+f"(c[3])
        : "r"(a[0]), "r"(a[1]), "r"(a[2]), "r"(a[3]),
          "r"(b[0]), "r"(b[1]));
}

__device__ __forceinline__ uint32_t smemu32(const void* p) {
    return (uint32_t)__cvta_generic_to_shared(p);
}

// Pack two fp32 into fp16x2 (RNE), lo = a, hi = b
__device__ __forceinline__ uint32_t pack_h2(float a, float b) {
    uint32_t r;
    asm("cvt.rn.f16x2.f32 %0, %1, %2;" : "=r"(r) : "f"(b), "f"(a));
    return r;
}

#define CP_ASYNC16(dst, src) \
    asm volatile("cp.async.cg.shared.global [%0], [%1], 16;\n" \
                 :: "r"(dst), "l"(src))
#define CP_COMMIT() asm volatile("cp.async.commit_group;\n" ::: "memory")

// ---------------------------------------------------------------------------
// fp32 -> fp16 conversion prep pass (8 elements / thread)
// ---------------------------------------------------------------------------
__global__ void f2h_kernel(const float* __restrict__ in,
                           __half* __restrict__ out, int n8)
{
    int i = blockIdx.x * blockDim.x + threadIdx.x;
    if (i < n8) {
        float4 v0 = ((const float4*)in)[i * 2];
        float4 v1 = ((const float4*)in)[i * 2 + 1];
        uint4 u;
        u.x = pack_h2(v0.x, v0.y);
        u.y = pack_h2(v0.z, v0.w);
        u.z = pack_h2(v1.x, v1.y);
        u.w = pack_h2(v1.z, v1.w);
        ((uint4*)out)[i] = u;
    }
}

// ---------------------------------------------------------------------------
// FP16 tensor-core GEMM: Y[M,N] = X[M,K] @ W[N,K]^T  (fp32 accumulate)
// BM=BN=128, BK=32 (2 x k16), 256 threads (8 warps, 2x4), warp tile 64x32.
// cp.async double buffer. Smem rows: 32 halfs content, stride 20 words
// (conflict-free for the m16n8k16 fragment pattern). OT = float or __half.
// ---------------------------------------------------------------------------
#define HST 20                        // smem row stride in 4B words
#define HSTAGE_W (128 * HST)          // words per operand per stage
#define HSMEM_BYTES (4 * HSTAGE_W * 4)   // 40960 B

template <typename OT>
__global__ __launch_bounds__(256) void gemm_h(
    const __half* __restrict__ X,
    const __half* __restrict__ W0, const __half* __restrict__ W1,
    const __half* __restrict__ W2,
    OT* __restrict__ Y0, OT* __restrict__ Y1, OT* __restrict__ Y2,
    int M, int N, int K)
{
    extern __shared__ __align__(16) uint32_t gsm[];

    const int z = blockIdx.z;
    const __half* W = (z == 0) ? W0 : (z == 1) ? W1 : W2;
    OT*           Y = (z == 0) ? Y0 : (z == 1) ? Y1 : Y2;

    const int tid  = threadIdx.x;
    const int lane = tid & 31;
    const int warp = tid >> 5;
    const int wm   = warp >> 2;       // 0..1
    const int wn   = warp & 3;        // 0..3
    const int grp  = lane >> 2;       // 0..7
    const int t4   = lane & 3;        // 0..3

    const int row0 = blockIdx.y * 128;
    const int col0 = blockIdx.x * 128;

    // cp.async mapping: thread covers one 16-half half-row chunk per operand
    const int lr = tid >> 1;          // 0..127
    const int lh = (tid & 1) * 16;    // 0 or 16 halfs
    const __half* Xg = X + (size_t)(row0 + lr) * K + lh;
    const __half* Wg = W + (size_t)(col0 + lr) * K + lh;
    const uint32_t sbase = smemu32(gsm);
    const uint32_t doff  = (uint32_t)(lr * HST + (tid & 1) * 8) * 4u;

    auto issue_stage = [&](int it, int s) {
        const int k0 = it * 32;
        uint32_t xd = sbase + (uint32_t)(s * 2)     * HSTAGE_W * 4u + doff;
        uint32_t wd = sbase + (uint32_t)(s * 2 + 1) * HSTAGE_W * 4u + doff;
        CP_ASYNC16(xd,      Xg + k0);
        CP_ASYNC16(xd + 16, Xg + k0 + 8);
        CP_ASYNC16(wd,      Wg + k0);
        CP_ASYNC16(wd + 16, Wg + k0 + 8);
        CP_COMMIT();
    };

    float acc[4][4][4] = {};

    const int niter = K / 32;         // 32
    issue_stage(0, 0);
    issue_stage(1, 1);

    for (int it = 0; it < niter; it++) {
        if (it + 1 < niter)
            asm volatile("cp.async.wait_group 1;" ::: "memory");
        else
            asm volatile("cp.async.wait_group 0;" ::: "memory");
        __syncthreads();

        const uint32_t* Xs = gsm + (size_t)((it & 1) * 2) * HSTAGE_W;
        const uint32_t* Ws = Xs + HSTAGE_W;

        #pragma unroll
        for (int ks = 0; ks < 2; ks++) {
            const int kw = ks * 8;
            uint32_t a[4][4], b[4][2];
            #pragma unroll
            for (int am = 0; am < 4; am++) {
                const uint32_t* p = Xs + (wm * 64 + am * 16 + grp) * HST + kw + t4;
                a[am][0] = p[0];
                a[am][1] = p[8 * HST];
                a[am][2] = p[4];
                a[am][3] = p[8 * HST + 4];
            }
            #pragma unroll
            for (int bn = 0; bn < 4; bn++) {
                const uint32_t* p = Ws + (wn * 32 + bn * 8 + grp) * HST + kw + t4;
                b[bn][0] = p[0];
                b[bn][1] = p[4];
            }
            #pragma unroll
            for (int am = 0; am < 4; am++)
                #pragma unroll
                for (int bn = 0; bn < 4; bn++)
                    mma_f16(acc[am][bn], a[am], b[bn]);
        }
        __syncthreads();
        if (it + 2 < niter) issue_stage(it + 2, it & 1);
    }

    #pragma unroll
    for (int am = 0; am < 4; am++) {
        const int r = row0 + wm * 64 + am * 16 + grp;
        #pragma unroll
        for (int bn = 0; bn < 4; bn++) {
            const int c = col0 + wn * 32 + bn * 8 + t4 * 2;
            if (sizeof(OT) == 4) {
                *(float2*)((float*)Y + (size_t)r * N + c) =
                    make_float2(acc[am][bn][0], acc[am][bn][1]);
                *(float2*)((float*)Y + (size_t)(r + 8) * N + c) =
                    make_float2(acc[am][bn][2], acc[am][bn][3]);
            } else {
                *(uint32_t*)((__half*)Y + (size_t)r * N + c) =
                    pack_h2(acc[am][bn][0], acc[am][bn][1]);
                *(uint32_t*)((__half*)Y + (size_t)(r + 8) * N + c) =
                    pack_h2(acc[am][bn][2], acc[am][bn][3]);
            }
        }
    }
}

// ---------------------------------------------------------------------------
// FP16 tensor-core flash attention (causal), fp32 softmax & accumulators.
// BQ=128, BKV=64, 256 threads (8 warps). Warp w owns q-rows [16w, 16w+16).
// All operands fp16 in smem (stride 36 words, conflict-free); S and O built
// with m16n8k16 mma; 1/sqrt(DH) applied to S post-mma (exact, power of 2).
// ---------------------------------------------------------------------------
#define FST 36   // word stride for all attention smem arrays
#define ATTN_SMEM_BYTES ((128 + 64 + 128 + 64) * FST * 4)   // 55296 B

__global__ __launch_bounds__(256) void attn_h(
    const __half* __restrict__ Qg, const __half* __restrict__ Kg,
    const __half* __restrict__ Vg, __half* __restrict__ Og)
{
    extern __shared__ __align__(16) uint32_t sm[];
    uint32_t* Qs = sm;                  // [128][32w] (i, d)
    uint32_t* Ks = Qs + 128 * FST;      // [64][32w]  (j, d)
    uint32_t* Ps = Ks + 64 * FST;       // [128][32w] (i, j)
    uint32_t* Vs = Ps + 128 * FST;      // [64][32w]  (c, j)  -- transposed V

    const int tid  = threadIdx.x;
    const int lane = tid & 31;
    const int warp = tid >> 5;
    const int grp  = lane >> 2;         // 0..7
    const int t4   = lane & 3;          // 0..3
    const int m0   = warp * 16;

    const int qt = (gridDim.x - 1) - blockIdx.x;   // heavy tiles first
    const int q0 = qt * 128;
    const int h  = blockIdx.y;
    const int b  = blockIdx.z;

    const __half* Qb = Qg + ((size_t)b * S_LEN + q0) * D_MODEL + h * DH;
    const __half* Kb = Kg + (size_t)b * S_LEN * D_MODEL + h * DH;
    const __half* Vb = Vg + (size_t)b * S_LEN * D_MODEL + h * DH;

    // Load Q tile (128 x 64 halfs): 16B chunks, 4 per thread
    #pragma unroll
    for (int r = 0; r < 4; r++) {
        int idx = tid + r * 256;
        int row = idx >> 3;             // 0..127
        int ch  = idx & 7;              // 0..7 (8 halfs each)
        uint4 v = *(const uint4*)(Qb + (size_t)row * D_MODEL + ch * 8);
        *(uint4*)(Qs + row * FST + ch * 4) = v;
    }

    float mr[2]  = {-INFINITY, -INFINITY};
    float lr_[2] = {0.f, 0.f};
    float o[8][4];
    #pragma unroll
    for (int n = 0; n < 8; n++)
        #pragma unroll
        for (int r = 0; r < 4; r++) o[n][r] = 0.f;

    // V transpose mapping: warp c-group, lane j-pair
    const int vjp = lane;               // j-pair 0..31
    const int vc0 = warp * 8;           // c 0..56

    const int ntiles = 2 * qt + 2;
    for (int kt = 0; kt < ntiles; kt++) {
        const int k0 = kt * 64;
        __syncthreads();

        // K tile (64 x 64 halfs): 2 chunks per thread
        #pragma unroll
        for (int r = 0; r < 2; r++) {
            int idx = tid + r * 256;
            int row = idx >> 3;
            int ch  = idx & 7;
            uint4 v = *(const uint4*)(Kb + (size_t)(k0 + row) * D_MODEL + ch * 8);
            *(uint4*)(Ks + row * FST + ch * 4) = v;
        }
        // V tile transposed into Vs[c][j]
        {
            const ushort* v0 = (const ushort*)(Vb + (size_t)(k0 + vjp * 2)     * D_MODEL + vc0);
            const ushort* v1 = (const ushort*)(Vb + (size_t)(k0 + vjp * 2 + 1) * D_MODEL + vc0);
            uint4 a0 = *(const uint4*)v0;
            uint4 a1 = *(const uint4*)v1;
            const ushort* u0 = (const ushort*)&a0;
            const ushort* u1 = (const ushort*)&a1;
            #pragma unroll
            for (int cc = 0; cc < 8; cc++)
                Vs[(vc0 + cc) * FST + vjp] = (uint32_t)u0[cc] | ((uint32_t)u1[cc] << 16);
        }
        __syncthreads();

        const bool active = (k0 <= q0 + m0 + 15);
        if (active) {
            // ---- S = Q K^T (fp16 mma, k16 x 4) ----
            float s[8][4];
            #pragma unroll
            for (int n = 0; n < 8; n++)
                #pragma unroll
                for (int r = 0; r < 4; r++) s[n][r] = 0.f;

            #pragma unroll
            for (int ks = 0; ks < 4; ks++) {
                const int kw = ks * 8;
                uint32_t a[4];
                const uint32_t* p = Qs + (m0 + grp) * FST + kw + t4;
                a[0] = p[0];
                a[1] = p[8 * FST];
                a[2] = p[4];
                a[3] = p[8 * FST + 4];
                #pragma unroll
                for (int n = 0; n < 8; n++) {
                    const uint32_t* q = Ks + (n * 8 + grp) * FST + kw + t4;
                    uint32_t bf[2] = {q[0], q[4]};
                    mma_f16(s[n], a, bf);
                }
            }
            #pragma unroll
            for (int n = 0; n < 8; n++) {
                s[n][0] *= 0.125f; s[n][1] *= 0.125f;
                s[n][2] *= 0.125f; s[n][3] *= 0.125f;
            }

            // ---- causal mask (only when tile clips this warp's rows) ----
            if (k0 + 63 > q0 + m0) {
                const int i0 = q0 + m0 + grp, i1 = i0 + 8;
                #pragma unroll
                for (int n = 0; n < 8; n++) {
                    const int j0 = k0 + n * 8 + t4 * 2;
                    if (j0     > i0) s[n][0] = -INFINITY;
                    if (j0 + 1 > i0) s[n][1] = -INFINITY;
                    if (j0     > i1) s[n][2] = -INFINITY;
                    if (j0 + 1 > i1) s[n][3] = -INFINITY;
                }
            }

            // ---- online softmax (rows grp, grp+8; quad shuffles) ----
            float ml0 = -INFINITY, ml1 = -INFINITY;
            #pragma unroll
            for (int n = 0; n < 8; n++) {
                ml0 = fmaxf(ml0, fmaxf(s[n][0], s[n][1]));
                ml1 = fmaxf(ml1, fmaxf(s[n][2], s[n][3]));
            }
            ml0 = fmaxf(ml0, __shfl_xor_sync(0xffffffffu, ml0, 1));
            ml0 = fmaxf(ml0, __shfl_xor_sync(0xffffffffu, ml0, 2));
            ml1 = fmaxf(ml1, __shfl_xor_sync(0xffffffffu, ml1, 1));
            ml1 = fmaxf(ml1, __shfl_xor_sync(0xffffffffu, ml1, 2));

            const float mn0 = fmaxf(mr[0], ml0);
            const float mn1 = fmaxf(mr[1], ml1);
            const float al0 = __expf(mr[0] - mn0);
            const float al1 = __expf(mr[1] - mn1);
            mr[0] = mn0; mr[1] = mn1;

            float ps0 = 0.f, ps1 = 0.f;
            #pragma unroll
            for (int n = 0; n < 8; n++) {
                s[n][0] = __expf(s[n][0] - mn0);
                s[n][1] = __expf(s[n][1] - mn0);
                s[n][2] = __expf(s[n][2] - mn1);
                s[n][3] = __expf(s[n][3] - mn1);
                ps0 += s[n][0] + s[n][1];
                ps1 += s[n][2] + s[n][3];
            }
            ps0 += __shfl_xor_sync(0xffffffffu, ps0, 1);
            ps0 += __shfl_xor_sync(0xffffffffu, ps0, 2);
            ps1 += __shfl_xor_sync(0xffffffffu, ps1, 1);
            ps1 += __shfl_xor_sync(0xffffffffu, ps1, 2);
            lr_[0] = lr_[0] * al0 + ps0;
            lr_[1] = lr_[1] * al1 + ps1;

            #pragma unroll
            for (int n = 0; n < 8; n++) {
                o[n][0] *= al0; o[n][1] *= al0;
                o[n][2] *= al1; o[n][3] *= al1;
            }

            // ---- P -> smem (fp16), warp-private rows ----
            #pragma unroll
            for (int n = 0; n < 8; n++) {
                Ps[(m0 + grp)     * FST + n * 4 + t4] = pack_h2(s[n][0], s[n][1]);
                Ps[(m0 + grp + 8) * FST + n * 4 + t4] = pack_h2(s[n][2], s[n][3]);
            }
            __syncwarp();

            // ---- O += P V (fp16 mma, k16 x 4 over j) ----
            #pragma unroll
            for (int ks = 0; ks < 4; ks++) {
                const int jw = ks * 8;
                uint32_t a[4];
                const uint32_t* p = Ps + (m0 + grp) * FST + jw + t4;
                a[0] = p[0];
                a[1] = p[8 * FST];
                a[2] = p[4];
                a[3] = p[8 * FST + 4];
                #pragma unroll
                for (int n = 0; n < 8; n++) {
                    const uint32_t* q = Vs + (n * 8 + grp) * FST + jw + t4;
                    uint32_t bf[2] = {q[0], q[4]};
                    mma_f16(o[n], a, bf);
                }
            }
        }
    }

    // ---- normalize (fp32) + store fp16 ----
    const float inv0 = 1.f / lr_[0];
    const float inv1 = 1.f / lr_[1];
    __half* Ob = Og + ((size_t)b * S_LEN + q0 + m0) * D_MODEL + h * DH;
    #pragma unroll
    for (int n = 0; n < 8; n++) {
        const int c = n * 8 + t4 * 2;
        *(uint32_t*)(Ob + (size_t)grp * D_MODEL + c) =
            pack_h2(o[n][0] * inv0, o[n][1] * inv0);
        *(uint32_t*)(Ob + (size_t)(grp + 8) * D_MODEL + c) =
            pack_h2(o[n][2] * inv1, o[n][3] * inv1);
    }
}

// ---------------------------------------------------------------------------
// Launch
// ---------------------------------------------------------------------------
extern "C" void kernel_launch(void* const* d_in, const int* in_sizes, int n_in,
                              void* d_out, int out_size)
{
    const float* x  = (const float*)d_in[0];
    const float* Wq = (const float*)d_in[1];
    const float* Wk = (const float*)d_in[2];
    const float* Wv = (const float*)d_in[3];
    const float* Wo = (const float*)d_in[4];
    float* out = (float*)d_out;

    __half *q, *k, *v, *att, *xh, *wh;
    cudaGetSymbolAddress((void**)&q,   g_qh);
    cudaGetSymbolAddress((void**)&k,   g_kh);
    cudaGetSymbolAddress((void**)&v,   g_vh);
    cudaGetSymbolAddress((void**)&att, g_atth);
    cudaGetSymbolAddress((void**)&xh,  g_xh);
    cudaGetSymbolAddress((void**)&wh,  g_wh);
    __half* wq = wh;
    __half* wk = wh + 1 * (size_t)D_MODEL * D_MODEL;
    __half* wv = wh + 2 * (size_t)D_MODEL * D_MODEL;
    __half* wo = wh + 3 * (size_t)D_MODEL * D_MODEL;

    cudaFuncSetAttribute(gemm_h<__half>,
                         cudaFuncAttributeMaxDynamicSharedMemorySize, HSMEM_BYTES);
    cudaFuncSetAttribute(gemm_h<float>,
                         cudaFuncAttributeMaxDynamicSharedMemorySize, HSMEM_BYTES);
    cudaFuncSetAttribute(attn_h,
                         cudaFuncAttributeMaxDynamicSharedMemorySize, ATTN_SMEM_BYTES);

    // fp32 -> fp16 prep (rne)
    const int NX = M_ROWS * D_MODEL / 8, NW = D_MODEL * D_MODEL / 8;
    f2h_kernel<<<(NX + 255) / 256, 256>>>(x,  xh, NX);
    f2h_kernel<<<(NW + 255) / 256, 256>>>(Wq, wq, NW);
    f2h_kernel<<<(NW + 255) / 256, 256>>>(Wk, wk, NW);
    f2h_kernel<<<(NW + 255) / 256, 256>>>(Wv, wv, NW);
    f2h_kernel<<<(NW + 255) / 256, 256>>>(Wo, wo, NW);

    // Fused QKV projections (fp16 out)
    dim3 gq(D_MODEL / 128, M_ROWS / 128, 3);   // (8, 32, 3)
    gemm_h<__half><<<gq, 256, HSMEM_BYTES>>>(xh, wq, wk, wv, q, k, v,
                                             M_ROWS, D_MODEL, D_MODEL);

    attn_h<<<dim3(S_LEN / 128, NH, BATCH), 256, ATTN_SMEM_BYTES>>>(q, k, v, att);

    // O projection (fp32 out to d_out)
    dim3 go(D_MODEL / 128, M_ROWS / 128, 1);
    gemm_h<float><<<go, 256, HSMEM_BYTES>>>(att, wo, wo, wo, out, out, out,
                                            M_ROWS, D_MODEL, D_MODEL);
}

// round 9
// speedup vs baseline: 5.5304x; 1.1373x over previous
#include <cuda_runtime.h>
#include <cuda_fp16.h>
#include <math.h>
#include <stdint.h>

#define S_LEN   2048
#define D_MODEL 1024
#define NH      16
#define DH      64
#define BATCH   2
#define M_ROWS  (BATCH * S_LEN)   // 4096

// ---------------------------------------------------------------------------
// Scratch (device globals: allocation-free, graph-capture safe)
// ---------------------------------------------------------------------------
__device__ __half g_qh[M_ROWS * D_MODEL];
__device__ __half g_kh[M_ROWS * D_MODEL];
__device__ __half g_vh[M_ROWS * D_MODEL];
__device__ __half g_atth[M_ROWS * D_MODEL];
__device__ __half g_xh[M_ROWS * D_MODEL];
__device__ __half g_wh[4][D_MODEL * D_MODEL];

// ---------------------------------------------------------------------------
// Helpers
// ---------------------------------------------------------------------------
__device__ __forceinline__ void mma_f16(float* c, const uint32_t* a,
                                        const uint32_t* b) {
    asm volatile(
        "mma.sync.aligned.m16n8k16.row.col.f32.f16.f16.f32 "
        "{%0,%1,%2,%3}, {%4,%5,%6,%7}, {%8,%9}, {%0,%1,%2,%3};\n"
        : "+f"(c[0]), "+f"(c[1]), "+f"(c[2]), "+f"(c[3])
        : "r"(a[0]), "r"(a[1]), "r"(a[2]), "r"(a[3]),
          "r"(b[0]), "r"(b[1]));
}

#define LDSM_X4(r0, r1, r2, r3, addr) \
    asm volatile("ldmatrix.sync.aligned.m8n8.x4.shared.b16 {%0,%1,%2,%3}, [%4];" \
                 : "=r"(r0), "=r"(r1), "=r"(r2), "=r"(r3) : "r"(addr))

__device__ __forceinline__ uint32_t smemu32(const void* p) {
    return (uint32_t)__cvta_generic_to_shared(p);
}

// Pack two fp32 into fp16x2 (RNE), lo = a, hi = b
__device__ __forceinline__ uint32_t pack_h2(float a, float b) {
    uint32_t r;
    asm("cvt.rn.f16x2.f32 %0, %1, %2;" : "=r"(r) : "f"(b), "f"(a));
    return r;
}

#define CP_ASYNC16(dst, src) \
    asm volatile("cp.async.cg.shared.global [%0], [%1], 16;\n" \
                 :: "r"(dst), "l"(src))
#define CP_COMMIT() asm volatile("cp.async.commit_group;\n" ::: "memory")

// ---------------------------------------------------------------------------
// Fused fp32 -> fp16 prep: grid.y selects tensor (0=X, 1..4=W)
// ---------------------------------------------------------------------------
#define NX8 (M_ROWS * D_MODEL / 8)
#define NW8 (D_MODEL * D_MODEL / 8)

__global__ void f2h5_kernel(const float* __restrict__ x,
                            const float* __restrict__ wq,
                            const float* __restrict__ wk,
                            const float* __restrict__ wv,
                            const float* __restrict__ wo,
                            __half* __restrict__ xh,
                            __half* __restrict__ wh)
{
    const int z = blockIdx.y;
    const int i = blockIdx.x * blockDim.x + threadIdx.x;
    const float* src;
    __half* dst;
    int n8;
    if (z == 0) { src = x; dst = xh; n8 = NX8; }
    else {
        src = (z == 1) ? wq : (z == 2) ? wk : (z == 3) ? wv : wo;
        dst = wh + (size_t)(z - 1) * D_MODEL * D_MODEL;
        n8 = NW8;
    }
    if (i < n8) {
        float4 v0 = ((const float4*)src)[i * 2];
        float4 v1 = ((const float4*)src)[i * 2 + 1];
        uint4 u;
        u.x = pack_h2(v0.x, v0.y);
        u.y = pack_h2(v0.z, v0.w);
        u.z = pack_h2(v1.x, v1.y);
        u.w = pack_h2(v1.z, v1.w);
        ((uint4*)dst)[i] = u;
    }
}

// ---------------------------------------------------------------------------
// FP16 tensor-core GEMM: Y[M,N] = X[M,K] @ W[N,K]^T  (fp32 accumulate)
// BM=BN=128, BK=32, 256 threads (8 warps, 2x4), warp tile 64x32.
// cp.async double buffer; fragments via ldmatrix.x4 (conflict-free stride 20).
// ---------------------------------------------------------------------------
#define HST 20                        // smem row stride in 4B words
#define HSTAGE_W (128 * HST)          // words per operand per stage
#define HSMEM_BYTES (4 * HSTAGE_W * 4)   // 40960 B

template <typename OT>
__global__ __launch_bounds__(256) void gemm_h(
    const __half* __restrict__ X,
    const __half* __restrict__ W0, const __half* __restrict__ W1,
    const __half* __restrict__ W2,
    OT* __restrict__ Y0, OT* __restrict__ Y1, OT* __restrict__ Y2,
    int M, int N, int K)
{
    extern __shared__ __align__(16) uint32_t gsm[];

    const int z = blockIdx.z;
    const __half* W = (z == 0) ? W0 : (z == 1) ? W1 : W2;
    OT*           Y = (z == 0) ? Y0 : (z == 1) ? Y1 : Y2;

    const int tid  = threadIdx.x;
    const int lane = tid & 31;
    const int warp = tid >> 5;
    const int wm   = warp >> 2;       // 0..1
    const int wn   = warp & 3;        // 0..3
    const int grp  = lane >> 2;       // 0..7
    const int t4   = lane & 3;        // 0..3

    const int row0 = blockIdx.y * 128;
    const int col0 = blockIdx.x * 128;

    // cp.async mapping: thread covers one 16-half chunk per operand
    const int lr = tid >> 1;          // 0..127
    const int lh = (tid & 1) * 16;    // 0 or 16 halfs
    const __half* Xg = X + (size_t)(row0 + lr) * K + lh;
    const __half* Wg = W + (size_t)(col0 + lr) * K + lh;
    const uint32_t sbase = smemu32(gsm);
    const uint32_t doff  = (uint32_t)(lr * HST + (tid & 1) * 8) * 4u;

    auto issue_stage = [&](int it, int s) {
        const int k0 = it * 32;
        uint32_t xd = sbase + (uint32_t)(s * 2)     * HSTAGE_W * 4u + doff;
        uint32_t wd = sbase + (uint32_t)(s * 2 + 1) * HSTAGE_W * 4u + doff;
        CP_ASYNC16(xd,      Xg + k0);
        CP_ASYNC16(xd + 16, Xg + k0 + 8);
        CP_ASYNC16(wd,      Wg + k0);
        CP_ASYNC16(wd + 16, Wg + k0 + 8);
        CP_COMMIT();
    };

    // ldmatrix lane offsets (bytes)
    const uint32_t aoff = (uint32_t)((wm * 64 + (lane & 15)) * HST * 4
                                     + ((lane >> 4) & 1) * 16);
    const uint32_t boff = (uint32_t)((wn * 32 + (lane & 7) + ((lane >> 4) << 3))
                                     * HST * 4 + ((lane >> 3) & 1) * 16);

    float acc[4][4][4] = {};

    const int niter = K / 32;         // 32
    issue_stage(0, 0);
    issue_stage(1, 1);

    for (int it = 0; it < niter; it++) {
        if (it + 1 < niter)
            asm volatile("cp.async.wait_group 1;" ::: "memory");
        else
            asm volatile("cp.async.wait_group 0;" ::: "memory");
        __syncthreads();

        const uint32_t xsb = sbase + (uint32_t)((it & 1) * 2) * HSTAGE_W * 4u;
        const uint32_t wsb = xsb + HSTAGE_W * 4u;

        #pragma unroll
        for (int ks = 0; ks < 2; ks++) {
            const uint32_t kb = ks * 32;   // 8 words = 16 halfs
            uint32_t a[4][4], b[2][4];
            #pragma unroll
            for (int am = 0; am < 4; am++)
                LDSM_X4(a[am][0], a[am][1], a[am][2], a[am][3],
                        xsb + aoff + (uint32_t)(am * 16 * HST * 4) + kb);
            #pragma unroll
            for (int bp = 0; bp < 2; bp++)
                LDSM_X4(b[bp][0], b[bp][1], b[bp][2], b[bp][3],
                        wsb + boff + (uint32_t)(bp * 16 * HST * 4) + kb);
            #pragma unroll
            for (int am = 0; am < 4; am++)
                #pragma unroll
                for (int bn = 0; bn < 4; bn++)
                    mma_f16(acc[am][bn], a[am], &b[bn >> 1][(bn & 1) * 2]);
        }
        __syncthreads();
        if (it + 2 < niter) issue_stage(it + 2, it & 1);
    }

    #pragma unroll
    for (int am = 0; am < 4; am++) {
        const int r = row0 + wm * 64 + am * 16 + grp;
        #pragma unroll
        for (int bn = 0; bn < 4; bn++) {
            const int c = col0 + wn * 32 + bn * 8 + t4 * 2;
            if (sizeof(OT) == 4) {
                *(float2*)((float*)Y + (size_t)r * N + c) =
                    make_float2(acc[am][bn][0], acc[am][bn][1]);
                *(float2*)((float*)Y + (size_t)(r + 8) * N + c) =
                    make_float2(acc[am][bn][2], acc[am][bn][3]);
            } else {
                *(uint32_t*)((__half*)Y + (size_t)r * N + c) =
                    pack_h2(acc[am][bn][0], acc[am][bn][1]);
                *(uint32_t*)((__half*)Y + (size_t)(r + 8) * N + c) =
                    pack_h2(acc[am][bn][2], acc[am][bn][3]);
            }
        }
    }
}

// ---------------------------------------------------------------------------
// FP16 flash attention (causal): ldmatrix fragments, register-direct P->PV
// (S C-fragment == PV A-fragment layout), fp32 softmax & accumulators.
// BQ=128, BKV=64, 256 threads (8 warps); warp w owns q-rows [16w, 16w+16).
// ---------------------------------------------------------------------------
#define FST 36   // word stride (ldmatrix conflict-free: banks 4r)
#define ATTN_SMEM_BYTES ((128 + 64 + 64) * FST * 4)   // 36864 B

__global__ __launch_bounds__(256) void attn_h(
    const __half* __restrict__ Qg, const __half* __restrict__ Kg,
    const __half* __restrict__ Vg, __half* __restrict__ Og)
{
    extern __shared__ __align__(16) uint32_t sm[];
    uint32_t* Qs = sm;                  // [128][32w] (i, d)
    uint32_t* Ks = Qs + 128 * FST;      // [64][32w]  (j, d)
    uint32_t* Vs = Ks + 64 * FST;       // [64][32w]  (c, j-pairs) transposed V

    const int tid  = threadIdx.x;
    const int lane = tid & 31;
    const int warp = tid >> 5;
    const int grp  = lane >> 2;         // 0..7
    const int t4   = lane & 3;          // 0..3
    const int m0   = warp * 16;

    const int qt = (gridDim.x - 1) - blockIdx.x;   // heavy tiles first
    const int q0 = qt * 128;
    const int h  = blockIdx.y;
    const int b  = blockIdx.z;

    const __half* Qb = Qg + ((size_t)b * S_LEN + q0) * D_MODEL + h * DH;
    const __half* Kb = Kg + (size_t)b * S_LEN * D_MODEL + h * DH;
    const __half* Vb = Vg + (size_t)b * S_LEN * D_MODEL + h * DH;

    // ldmatrix lane offsets (bytes)
    const uint32_t sQ = smemu32(Qs), sK = smemu32(Ks), sV = smemu32(Vs);
    const uint32_t aoff = (uint32_t)((lane & 15) * FST * 4
                                     + ((lane >> 4) & 1) * 16);
    const uint32_t boff = (uint32_t)(((lane & 7) + ((lane >> 4) << 3)) * FST * 4
                                     + ((lane >> 3) & 1) * 16);

    // Load Q tile (128 x 64 halfs)
    #pragma unroll
    for (int r = 0; r < 4; r++) {
        int idx = tid + r * 256;
        int row = idx >> 3;             // 0..127
        int ch  = idx & 7;              // 8 halfs each
        uint4 v = *(const uint4*)(Qb + (size_t)row * D_MODEL + ch * 8);
        *(uint4*)(Qs + row * FST + ch * 4) = v;
    }

    float mr[2]  = {-INFINITY, -INFINITY};
    float lr_[2] = {0.f, 0.f};
    float o[8][4];
    #pragma unroll
    for (int n = 0; n < 8; n++)
        #pragma unroll
        for (int r = 0; r < 4; r++) o[n][r] = 0.f;

    const int vjp = lane;               // j-pair 0..31
    const int vc0 = warp * 8;           // c base

    const int ntiles = 2 * qt + 2;
    for (int kt = 0; kt < ntiles; kt++) {
        const int k0 = kt * 64;
        __syncthreads();   // protect Ks/Vs against previous iter's reads

        // K tile (64 x 64 halfs)
        #pragma unroll
        for (int r = 0; r < 2; r++) {
            int idx = tid + r * 256;
            int row = idx >> 3;
            int ch  = idx & 7;
            uint4 v = *(const uint4*)(Kb + (size_t)(k0 + row) * D_MODEL + ch * 8);
            *(uint4*)(Ks + row * FST + ch * 4) = v;
        }
        // V tile transposed into Vs[c][j-pair]
        {
            const ushort* v0 = (const ushort*)(Vb + (size_t)(k0 + vjp * 2)     * D_MODEL + vc0);
            const ushort* v1 = (const ushort*)(Vb + (size_t)(k0 + vjp * 2 + 1) * D_MODEL + vc0);
            uint4 a0 = *(const uint4*)v0;
            uint4 a1 = *(const uint4*)v1;
            const ushort* u0 = (const ushort*)&a0;
            const ushort* u1 = (const ushort*)&a1;
            #pragma unroll
            for (int cc = 0; cc < 8; cc++)
                Vs[(vc0 + cc) * FST + vjp] = (uint32_t)u0[cc] | ((uint32_t)u1[cc] << 16);
        }
        __syncthreads();

        const bool active = (k0 <= q0 + m0 + 15);
        if (active) {
            // ---- S = Q K^T ----
            float s[8][4];
            #pragma unroll
            for (int n = 0; n < 8; n++)
                #pragma unroll
                for (int r = 0; r < 4; r++) s[n][r] = 0.f;

            #pragma unroll
            for (int ks = 0; ks < 4; ks++) {
                const uint32_t kb = ks * 32;
                uint32_t a[4], bk[4][4];
                LDSM_X4(a[0], a[1], a[2], a[3],
                        sQ + (uint32_t)(m0 * FST * 4) + aoff + kb);
                #pragma unroll
                for (int np = 0; np < 4; np++)
                    LDSM_X4(bk[np][0], bk[np][1], bk[np][2], bk[np][3],
                            sK + boff + (uint32_t)(np * 16 * FST * 4) + kb);
                #pragma unroll
                for (int n = 0; n < 8; n++)
                    mma_f16(s[n], a, &bk[n >> 1][(n & 1) * 2]);
            }
            #pragma unroll
            for (int n = 0; n < 8; n++) {
                s[n][0] *= 0.125f; s[n][1] *= 0.125f;
                s[n][2] *= 0.125f; s[n][3] *= 0.125f;
            }

            // ---- causal mask (only when tile clips this warp's rows) ----
            if (k0 + 63 > q0 + m0) {
                const int i0 = q0 + m0 + grp, i1 = i0 + 8;
                #pragma unroll
                for (int n = 0; n < 8; n++) {
                    const int j0 = k0 + n * 8 + t4 * 2;
                    if (j0     > i0) s[n][0] = -INFINITY;
                    if (j0 + 1 > i0) s[n][1] = -INFINITY;
                    if (j0     > i1) s[n][2] = -INFINITY;
                    if (j0 + 1 > i1) s[n][3] = -INFINITY;
                }
            }

            // ---- online softmax (rows grp, grp+8; quad shuffles) ----
            float ml0 = -INFINITY, ml1 = -INFINITY;
            #pragma unroll
            for (int n = 0; n < 8; n++) {
                ml0 = fmaxf(ml0, fmaxf(s[n][0], s[n][1]));
                ml1 = fmaxf(ml1, fmaxf(s[n][2], s[n][3]));
            }
            ml0 = fmaxf(ml0, __shfl_xor_sync(0xffffffffu, ml0, 1));
            ml0 = fmaxf(ml0, __shfl_xor_sync(0xffffffffu, ml0, 2));
            ml1 = fmaxf(ml1, __shfl_xor_sync(0xffffffffu, ml1, 1));
            ml1 = fmaxf(ml1, __shfl_xor_sync(0xffffffffu, ml1, 2));

            const float mn0 = fmaxf(mr[0], ml0);
            const float mn1 = fmaxf(mr[1], ml1);
            const float al0 = __expf(mr[0] - mn0);
            const float al1 = __expf(mr[1] - mn1);
            mr[0] = mn0; mr[1] = mn1;

            float ps0 = 0.f, ps1 = 0.f;
            #pragma unroll
            for (int n = 0; n < 8; n++) {
                s[n][0] = __expf(s[n][0] - mn0);
                s[n][1] = __expf(s[n][1] - mn0);
                s[n][2] = __expf(s[n][2] - mn1);
                s[n][3] = __expf(s[n][3] - mn1);
                ps0 += s[n][0] + s[n][1];
                ps1 += s[n][2] + s[n][3];
            }
            ps0 += __shfl_xor_sync(0xffffffffu, ps0, 1);
            ps0 += __shfl_xor_sync(0xffffffffu, ps0, 2);
            ps1 += __shfl_xor_sync(0xffffffffu, ps1, 1);
            ps1 += __shfl_xor_sync(0xffffffffu, ps1, 2);
            lr_[0] = lr_[0] * al0 + ps0;
            lr_[1] = lr_[1] * al1 + ps1;

            #pragma unroll
            for (int n = 0; n < 8; n++) {
                o[n][0] *= al0; o[n][1] *= al0;
                o[n][2] *= al1; o[n][3] *= al1;
            }

            // ---- O += P V : P stays in registers (C-frag == A-frag) ----
            #pragma unroll
            for (int ks = 0; ks < 4; ks++) {
                const uint32_t kb = ks * 32;
                uint32_t ap[4], bv[4][4];
                ap[0] = pack_h2(s[2 * ks][0],     s[2 * ks][1]);
                ap[1] = pack_h2(s[2 * ks][2],     s[2 * ks][3]);
                ap[2] = pack_h2(s[2 * ks + 1][0], s[2 * ks + 1][1]);
                ap[3] = pack_h2(s[2 * ks + 1][2], s[2 * ks + 1][3]);
                #pragma unroll
                for (int np = 0; np < 4; np++)
                    LDSM_X4(bv[np][0], bv[np][1], bv[np][2], bv[np][3],
                            sV + boff + (uint32_t)(np * 16 * FST * 4) + kb);
                #pragma unroll
                for (int n = 0; n < 8; n++)
                    mma_f16(o[n], ap, &bv[n >> 1][(n & 1) * 2]);
            }
        }
    }

    // ---- normalize (fp32) + store fp16 ----
    const float inv0 = 1.f / lr_[0];
    const float inv1 = 1.f / lr_[1];
    __half* Ob = Og + ((size_t)b * S_LEN + q0 + m0) * D_MODEL + h * DH;
    #pragma unroll
    for (int n = 0; n < 8; n++) {
        const int c = n * 8 + t4 * 2;
        *(uint32_t*)(Ob + (size_t)grp * D_MODEL + c) =
            pack_h2(o[n][0] * inv0, o[n][1] * inv0);
        *(uint32_t*)(Ob + (size_t)(grp + 8) * D_MODEL + c) =
            pack_h2(o[n][2] * inv1, o[n][3] * inv1);
    }
}

// ---------------------------------------------------------------------------
// Launch
// ---------------------------------------------------------------------------
extern "C" void kernel_launch(void* const* d_in, const int* in_sizes, int n_in,
                              void* d_out, int out_size)
{
    const float* x  = (const float*)d_in[0];
    const float* Wq = (const float*)d_in[1];
    const float* Wk = (const float*)d_in[2];
    const float* Wv = (const float*)d_in[3];
    const float* Wo = (const float*)d_in[4];
    float* out = (float*)d_out;

    __half *q, *k, *v, *att, *xh, *wh;
    cudaGetSymbolAddress((void**)&q,   g_qh);
    cudaGetSymbolAddress((void**)&k,   g_kh);
    cudaGetSymbolAddress((void**)&v,   g_vh);
    cudaGetSymbolAddress((void**)&att, g_atth);
    cudaGetSymbolAddress((void**)&xh,  g_xh);
    cudaGetSymbolAddress((void**)&wh,  g_wh);
    __half* wq = wh;
    __half* wk = wh + 1 * (size_t)D_MODEL * D_MODEL;
    __half* wv = wh + 2 * (size_t)D_MODEL * D_MODEL;
    __half* wo = wh + 3 * (size_t)D_MODEL * D_MODEL;

    cudaFuncSetAttribute(gemm_h<__half>,
                         cudaFuncAttributeMaxDynamicSharedMemorySize, HSMEM_BYTES);
    cudaFuncSetAttribute(gemm_h<float>,
                         cudaFuncAttributeMaxDynamicSharedMemorySize, HSMEM_BYTES);
    cudaFuncSetAttribute(attn_h,
                         cudaFuncAttributeMaxDynamicSharedMemorySize, ATTN_SMEM_BYTES);

    // fp32 -> fp16 prep, one launch (grid.y selects tensor)
    f2h5_kernel<<<dim3(NX8 / 256, 5), 256>>>(x, Wq, Wk, Wv, Wo, xh, wh);

    // Fused QKV projections (fp16 out)
    dim3 gq(D_MODEL / 128, M_ROWS / 128, 3);   // (8, 32, 3)
    gemm_h<__half><<<gq, 256, HSMEM_BYTES>>>(xh, wq, wk, wv, q, k, v,
                                             M_ROWS, D_MODEL, D_MODEL);

    attn_h<<<dim3(S_LEN / 128, NH, BATCH), 256, ATTN_SMEM_BYTES>>>(q, k, v, att);

    // O projection (fp32 out to d_out)
    dim3 go(D_MODEL / 128, M_ROWS / 128, 1);
    gemm_h<float><<<go, 256, HSMEM_BYTES>>>(att, wo, wo, wo, out, out, out,
                                            M_ROWS, D_MODEL, D_MODEL);
}

// round 10
// speedup vs baseline: 5.9229x; 1.0710x over previous
#include <cuda_runtime.h>
#include <cuda_fp16.h>
#include <math.h>
#include <stdint.h>

#define S_LEN   2048
#define D_MODEL 1024
#define NH      16
#define DH      64
#define BATCH   2
#define M_ROWS  (BATCH * S_LEN)   // 4096

// ---------------------------------------------------------------------------
// Scratch (device globals: allocation-free, graph-capture safe)
// ---------------------------------------------------------------------------
__device__ __half g_qh[M_ROWS * D_MODEL];
__device__ __half g_kh[M_ROWS * D_MODEL];
__device__ __half g_vh[M_ROWS * D_MODEL];
__device__ __half g_atth[M_ROWS * D_MODEL];
__device__ __half g_xh[M_ROWS * D_MODEL];
__device__ __half g_wh[4][D_MODEL * D_MODEL];

// ---------------------------------------------------------------------------
// Helpers
// ---------------------------------------------------------------------------
__device__ __forceinline__ void mma_f16(float* c, const uint32_t* a,
                                        const uint32_t* b) {
    asm volatile(
        "mma.sync.aligned.m16n8k16.row.col.f32.f16.f16.f32 "
        "{%0,%1,%2,%3}, {%4,%5,%6,%7}, {%8,%9}, {%0,%1,%2,%3};\n"
        : "+f"(c[0]), "+f"(c[1]), "+f"(c[2]), "+f"(c[3])
        : "r"(a[0]), "r"(a[1]), "r"(a[2]), "r"(a[3]),
          "r"(b[0]), "r"(b[1]));
}

#define LDSM_X4(r0, r1, r2, r3, addr) \
    asm volatile("ldmatrix.sync.aligned.m8n8.x4.shared.b16 {%0,%1,%2,%3}, [%4];" \
                 : "=r"(r0), "=r"(r1), "=r"(r2), "=r"(r3) : "r"(addr))

#define LDSM_X4_T(r0, r1, r2, r3, addr) \
    asm volatile("ldmatrix.sync.aligned.m8n8.x4.trans.shared.b16 {%0,%1,%2,%3}, [%4];" \
                 : "=r"(r0), "=r"(r1), "=r"(r2), "=r"(r3) : "r"(addr))

__device__ __forceinline__ uint32_t smemu32(const void* p) {
    return (uint32_t)__cvta_generic_to_shared(p);
}

// Pack two fp32 into fp16x2 (RNE), lo = a, hi = b
__device__ __forceinline__ uint32_t pack_h2(float a, float b) {
    uint32_t r;
    asm("cvt.rn.f16x2.f32 %0, %1, %2;" : "=r"(r) : "f"(b), "f"(a));
    return r;
}

#define CP_ASYNC16(dst, src) \
    asm volatile("cp.async.cg.shared.global [%0], [%1], 16;\n" \
                 :: "r"(dst), "l"(src))
#define CP_COMMIT() asm volatile("cp.async.commit_group;\n" ::: "memory")

// ---------------------------------------------------------------------------
// Fused fp32 -> fp16 prep: grid.y selects tensor (0=X, 1..4=W)
// ---------------------------------------------------------------------------
#define NX8 (M_ROWS * D_MODEL / 8)
#define NW8 (D_MODEL * D_MODEL / 8)

__global__ void f2h5_kernel(const float* __restrict__ x,
                            const float* __restrict__ wq,
                            const float* __restrict__ wk,
                            const float* __restrict__ wv,
                            const float* __restrict__ wo,
                            __half* __restrict__ xh,
                            __half* __restrict__ wh)
{
    const int z = blockIdx.y;
    const int i = blockIdx.x * blockDim.x + threadIdx.x;
    const float* src;
    __half* dst;
    int n8;
    if (z == 0) { src = x; dst = xh; n8 = NX8; }
    else {
        src = (z == 1) ? wq : (z == 2) ? wk : (z == 3) ? wv : wo;
        dst = wh + (size_t)(z - 1) * D_MODEL * D_MODEL;
        n8 = NW8;
    }
    if (i < n8) {
        float4 v0 = ((const float4*)src)[i * 2];
        float4 v1 = ((const float4*)src)[i * 2 + 1];
        uint4 u;
        u.x = pack_h2(v0.x, v0.y);
        u.y = pack_h2(v0.z, v0.w);
        u.z = pack_h2(v1.x, v1.y);
        u.w = pack_h2(v1.z, v1.w);
        ((uint4*)dst)[i] = u;
    }
}

// ---------------------------------------------------------------------------
// FP16 tensor-core GEMM: Y[M,N] = X[M,K] @ W[N,K]^T  (fp32 accumulate)
// BM=BN=128, BK=32, 256 threads (8 warps, 2x4), warp tile 64x32.
// 3-stage cp.async ring, ONE __syncthreads per iteration; ldmatrix.x4.
// ---------------------------------------------------------------------------
#define HST 20                        // smem row stride in 4B words
#define HSTAGE_W (128 * HST)          // words per operand per stage
#define HSMEM_BYTES (6 * HSTAGE_W * 4)   // 3 stages x 2 operands = 61440 B

template <typename OT>
__global__ __launch_bounds__(256) void gemm_h(
    const __half* __restrict__ X,
    const __half* __restrict__ W0, const __half* __restrict__ W1,
    const __half* __restrict__ W2,
    OT* __restrict__ Y0, OT* __restrict__ Y1, OT* __restrict__ Y2,
    int M, int N, int K)
{
    extern __shared__ __align__(16) uint32_t gsm[];

    const int z = blockIdx.z;
    const __half* W = (z == 0) ? W0 : (z == 1) ? W1 : W2;
    OT*           Y = (z == 0) ? Y0 : (z == 1) ? Y1 : Y2;

    const int tid  = threadIdx.x;
    const int lane = tid & 31;
    const int warp = tid >> 5;
    const int wm   = warp >> 2;       // 0..1
    const int wn   = warp & 3;        // 0..3
    const int grp  = lane >> 2;       // 0..7
    const int t4   = lane & 3;        // 0..3

    const int row0 = blockIdx.y * 128;
    const int col0 = blockIdx.x * 128;

    // cp.async mapping: thread covers one 16-half chunk per operand
    const int lr = tid >> 1;          // 0..127
    const int lh = (tid & 1) * 16;    // 0 or 16 halfs
    const __half* Xg = X + (size_t)(row0 + lr) * K + lh;
    const __half* Wg = W + (size_t)(col0 + lr) * K + lh;
    const uint32_t sbase = smemu32(gsm);
    const uint32_t doff  = (uint32_t)(lr * HST + (tid & 1) * 8) * 4u;

    auto issue_stage = [&](int it) {
        const int s  = it % 3;
        const int k0 = it * 32;
        uint32_t xd = sbase + (uint32_t)(s * 2)     * HSTAGE_W * 4u + doff;
        uint32_t wd = sbase + (uint32_t)(s * 2 + 1) * HSTAGE_W * 4u + doff;
        CP_ASYNC16(xd,      Xg + k0);
        CP_ASYNC16(xd + 16, Xg + k0 + 8);
        CP_ASYNC16(wd,      Wg + k0);
        CP_ASYNC16(wd + 16, Wg + k0 + 8);
        CP_COMMIT();
    };

    // ldmatrix lane offsets (bytes)
    const uint32_t aoff = (uint32_t)((wm * 64 + (lane & 15)) * HST * 4
                                     + ((lane >> 4) & 1) * 16);
    const uint32_t boff = (uint32_t)((wn * 32 + (lane & 7) + ((lane >> 4) << 3))
                                     * HST * 4 + ((lane >> 3) & 1) * 16);

    float acc[4][4][4] = {};

    const int niter = K / 32;         // 32
    issue_stage(0);
    issue_stage(1);

    for (int it = 0; it < niter; it++) {
        if (it + 1 < niter)
            asm volatile("cp.async.wait_group 1;" ::: "memory");
        else
            asm volatile("cp.async.wait_group 0;" ::: "memory");
        __syncthreads();
        if (it + 2 < niter) issue_stage(it + 2);   // safe: 3-stage ring

        const uint32_t xsb = sbase + (uint32_t)((it % 3) * 2) * HSTAGE_W * 4u;
        const uint32_t wsb = xsb + HSTAGE_W * 4u;

        #pragma unroll
        for (int ks = 0; ks < 2; ks++) {
            const uint32_t kb = ks * 32;   // 8 words = 16 halfs
            uint32_t a[4][4], b[2][4];
            #pragma unroll
            for (int am = 0; am < 4; am++)
                LDSM_X4(a[am][0], a[am][1], a[am][2], a[am][3],
                        xsb + aoff + (uint32_t)(am * 16 * HST * 4) + kb);
            #pragma unroll
            for (int bp = 0; bp < 2; bp++)
                LDSM_X4(b[bp][0], b[bp][1], b[bp][2], b[bp][3],
                        wsb + boff + (uint32_t)(bp * 16 * HST * 4) + kb);
            #pragma unroll
            for (int am = 0; am < 4; am++)
                #pragma unroll
                for (int bn = 0; bn < 4; bn++)
                    mma_f16(acc[am][bn], a[am], &b[bn >> 1][(bn & 1) * 2]);
        }
    }

    #pragma unroll
    for (int am = 0; am < 4; am++) {
        const int r = row0 + wm * 64 + am * 16 + grp;
        #pragma unroll
        for (int bn = 0; bn < 4; bn++) {
            const int c = col0 + wn * 32 + bn * 8 + t4 * 2;
            if (sizeof(OT) == 4) {
                *(float2*)((float*)Y + (size_t)r * N + c) =
                    make_float2(acc[am][bn][0], acc[am][bn][1]);
                *(float2*)((float*)Y + (size_t)(r + 8) * N + c) =
                    make_float2(acc[am][bn][2], acc[am][bn][3]);
            } else {
                *(uint32_t*)((__half*)Y + (size_t)r * N + c) =
                    pack_h2(acc[am][bn][0], acc[am][bn][1]);
                *(uint32_t*)((__half*)Y + (size_t)(r + 8) * N + c) =
                    pack_h2(acc[am][bn][2], acc[am][bn][3]);
            }
        }
    }
}

// ---------------------------------------------------------------------------
// FP16 flash attention (causal): 3-stage cp.async K+V ring (one sync/tile),
// ldmatrix fragments (V via ldmatrix.trans on row-major V), register-direct
// P->PV, fp32 softmax & accumulators.
// BQ=128, BKV=64, 256 threads (8 warps); warp w owns q-rows [16w, 16w+16).
// ---------------------------------------------------------------------------
#define FST 36   // word stride (ldmatrix conflict-free: banks 4r)
#define KVSTAGE_W (128 * FST)                    // K 64 rows + V 64 rows
#define ATTN_SMEM_BYTES ((128 * FST + 3 * KVSTAGE_W) * 4)   // 73728 B

__global__ __launch_bounds__(256) void attn_h(
    const __half* __restrict__ Qg, const __half* __restrict__ Kg,
    const __half* __restrict__ Vg, __half* __restrict__ Og)
{
    extern __shared__ __align__(16) uint32_t sm[];
    uint32_t* Qs = sm;                  // [128][32w] (i, d)

    const int tid  = threadIdx.x;
    const int lane = tid & 31;
    const int warp = tid >> 5;
    const int grp  = lane >> 2;         // 0..7
    const int t4   = lane & 3;          // 0..3
    const int m0   = warp * 16;

    const int qt = (gridDim.x - 1) - blockIdx.x;   // heavy tiles first
    const int q0 = qt * 128;
    const int h  = blockIdx.y;
    const int b  = blockIdx.z;

    const __half* Qb = Qg + ((size_t)b * S_LEN + q0) * D_MODEL + h * DH;
    const __half* Kb = Kg + (size_t)b * S_LEN * D_MODEL + h * DH;
    const __half* Vb = Vg + (size_t)b * S_LEN * D_MODEL + h * DH;

    const uint32_t sQ  = smemu32(Qs);
    const uint32_t sKV = sQ + 128 * FST * 4;

    // ldmatrix lane offsets (bytes)
    const uint32_t aoff = (uint32_t)((lane & 15) * FST * 4
                                     + ((lane >> 4) & 1) * 16);
    const uint32_t boff = (uint32_t)(((lane & 7) + ((lane >> 4) << 3)) * FST * 4
                                     + ((lane >> 3) & 1) * 16);
    // trans B-operand offsets for V (rows = j, 16B col select by lane>>4)
    const uint32_t voff = (uint32_t)((lane & 15) * FST * 4
                                     + ((lane >> 4) & 1) * 16);

    // cp.async mapping for K/V tiles: 2 chunks each per thread
    const int krow = tid >> 3;          // 0..31 base (2 rounds -> 64 rows)
    const int kch  = tid & 7;           // 16B chunk in row

    auto issue_kv = [&](int kt) {
        const int s  = kt % 3;
        const int k0 = kt * 64;
        const uint32_t base = sKV + (uint32_t)s * KVSTAGE_W * 4u;
        #pragma unroll
        for (int r = 0; r < 2; r++) {
            const int row = krow + r * 32;
            const uint32_t d = base + (uint32_t)(row * FST * 4 + kch * 16);
            CP_ASYNC16(d, Kb + (size_t)(k0 + row) * D_MODEL + kch * 8);
            CP_ASYNC16(d + (uint32_t)(64 * FST * 4),
                       Vb + (size_t)(k0 + row) * D_MODEL + kch * 8);
        }
        CP_COMMIT();
    };

    // Load Q tile (128 x 64 halfs)
    #pragma unroll
    for (int r = 0; r < 4; r++) {
        int idx = tid + r * 256;
        int row = idx >> 3;             // 0..127
        int ch  = idx & 7;              // 8 halfs each
        uint4 v = *(const uint4*)(Qb + (size_t)row * D_MODEL + ch * 8);
        *(uint4*)(Qs + row * FST + ch * 4) = v;
    }

    float mr[2]  = {-INFINITY, -INFINITY};
    float lr_[2] = {0.f, 0.f};
    float o[8][4];
    #pragma unroll
    for (int n = 0; n < 8; n++)
        #pragma unroll
        for (int r = 0; r < 4; r++) o[n][r] = 0.f;

    const int ntiles = 2 * qt + 2;
    issue_kv(0);
    if (ntiles > 1) issue_kv(1);

    for (int kt = 0; kt < ntiles; kt++) {
        if (kt + 1 < ntiles)
            asm volatile("cp.async.wait_group 1;" ::: "memory");
        else
            asm volatile("cp.async.wait_group 0;" ::: "memory");
        __syncthreads();
        if (kt + 2 < ntiles) issue_kv(kt + 2);   // safe: 3-stage ring

        const int k0 = kt * 64;
        const uint32_t sKst = sKV + (uint32_t)((kt % 3)) * KVSTAGE_W * 4u;
        const uint32_t sVst = sKst + (uint32_t)(64 * FST * 4);

        const bool active = (k0 <= q0 + m0 + 15);
        if (active) {
            // ---- S = Q K^T ----
            float s[8][4];
            #pragma unroll
            for (int n = 0; n < 8; n++)
                #pragma unroll
                for (int r = 0; r < 4; r++) s[n][r] = 0.f;

            #pragma unroll
            for (int ks = 0; ks < 4; ks++) {
                const uint32_t kb = ks * 32;
                uint32_t a[4], bk[4][4];
                LDSM_X4(a[0], a[1], a[2], a[3],
                        sQ + (uint32_t)(m0 * FST * 4) + aoff + kb);
                #pragma unroll
                for (int np = 0; np < 4; np++)
                    LDSM_X4(bk[np][0], bk[np][1], bk[np][2], bk[np][3],
                            sKst + boff + (uint32_t)(np * 16 * FST * 4) + kb);
                #pragma unroll
                for (int n = 0; n < 8; n++)
                    mma_f16(s[n], a, &bk[n >> 1][(n & 1) * 2]);
            }
            #pragma unroll
            for (int n = 0; n < 8; n++) {
                s[n][0] *= 0.125f; s[n][1] *= 0.125f;
                s[n][2] *= 0.125f; s[n][3] *= 0.125f;
            }

            // ---- causal mask (only when tile clips this warp's rows) ----
            if (k0 + 63 > q0 + m0) {
                const int i0 = q0 + m0 + grp, i1 = i0 + 8;
                #pragma unroll
                for (int n = 0; n < 8; n++) {
                    const int j0 = k0 + n * 8 + t4 * 2;
                    if (j0     > i0) s[n][0] = -INFINITY;
                    if (j0 + 1 > i0) s[n][1] = -INFINITY;
                    if (j0     > i1) s[n][2] = -INFINITY;
                    if (j0 + 1 > i1) s[n][3] = -INFINITY;
                }
            }

            // ---- online softmax (rows grp, grp+8; quad shuffles) ----
            float ml0 = -INFINITY, ml1 = -INFINITY;
            #pragma unroll
            for (int n = 0; n < 8; n++) {
                ml0 = fmaxf(ml0, fmaxf(s[n][0], s[n][1]));
                ml1 = fmaxf(ml1, fmaxf(s[n][2], s[n][3]));
            }
            ml0 = fmaxf(ml0, __shfl_xor_sync(0xffffffffu, ml0, 1));
            ml0 = fmaxf(ml0, __shfl_xor_sync(0xffffffffu, ml0, 2));
            ml1 = fmaxf(ml1, __shfl_xor_sync(0xffffffffu, ml1, 1));
            ml1 = fmaxf(ml1, __shfl_xor_sync(0xffffffffu, ml1, 2));

            const float mn0 = fmaxf(mr[0], ml0);
            const float mn1 = fmaxf(mr[1], ml1);
            const float al0 = __expf(mr[0] - mn0);
            const float al1 = __expf(mr[1] - mn1);
            mr[0] = mn0; mr[1] = mn1;

            float ps0 = 0.f, ps1 = 0.f;
            #pragma unroll
            for (int n = 0; n < 8; n++) {
                s[n][0] = __expf(s[n][0] - mn0);
                s[n][1] = __expf(s[n][1] - mn0);
                s[n][2] = __expf(s[n][2] - mn1);
                s[n][3] = __expf(s[n][3] - mn1);
                ps0 += s[n][0] + s[n][1];
                ps1 += s[n][2] + s[n][3];
            }
            ps0 += __shfl_xor_sync(0xffffffffu, ps0, 1);
            ps0 += __shfl_xor_sync(0xffffffffu, ps0, 2);
            ps1 += __shfl_xor_sync(0xffffffffu, ps1, 1);
            ps1 += __shfl_xor_sync(0xffffffffu, ps1, 2);
            lr_[0] = lr_[0] * al0 + ps0;
            lr_[1] = lr_[1] * al1 + ps1;

            #pragma unroll
            for (int n = 0; n < 8; n++) {
                o[n][0] *= al0; o[n][1] *= al0;
                o[n][2] *= al1; o[n][3] *= al1;
            }

            // ---- O += P V : P in registers; V B-frags via ldmatrix.trans ----
            #pragma unroll
            for (int ks = 0; ks < 4; ks++) {
                uint32_t ap[4], bv[4][4];
                ap[0] = pack_h2(s[2 * ks][0],     s[2 * ks][1]);
                ap[1] = pack_h2(s[2 * ks][2],     s[2 * ks][3]);
                ap[2] = pack_h2(s[2 * ks + 1][0], s[2 * ks + 1][1]);
                ap[3] = pack_h2(s[2 * ks + 1][2], s[2 * ks + 1][3]);
                const uint32_t vrow = sVst + voff + (uint32_t)(ks * 16 * FST * 4);
                #pragma unroll
                for (int np = 0; np < 4; np++)
                    LDSM_X4_T(bv[np][0], bv[np][1], bv[np][2], bv[np][3],
                              vrow + (uint32_t)(np * 32));
                #pragma unroll
                for (int n = 0; n < 8; n++)
                    mma_f16(o[n], ap, &bv[n >> 1][(n & 1) * 2]);
            }
        }
    }

    // ---- normalize (fp32) + store fp16 ----
    const float inv0 = 1.f / lr_[0];
    const float inv1 = 1.f / lr_[1];
    __half* Ob = Og + ((size_t)b * S_LEN + q0 + m0) * D_MODEL + h * DH;
    #pragma unroll
    for (int n = 0; n < 8; n++) {
        const int c = n * 8 + t4 * 2;
        *(uint32_t*)(Ob + (size_t)grp * D_MODEL + c) =
            pack_h2(o[n][0] * inv0, o[n][1] * inv0);
        *(uint32_t*)(Ob + (size_t)(grp + 8) * D_MODEL + c) =
            pack_h2(o[n][2] * inv1, o[n][3] * inv1);
    }
}

// ---------------------------------------------------------------------------
// Launch
// ---------------------------------------------------------------------------
extern "C" void kernel_launch(void* const* d_in, const int* in_sizes, int n_in,
                              void* d_out, int out_size)
{
    const float* x  = (const float*)d_in[0];
    const float* Wq = (const float*)d_in[1];
    const float* Wk = (const float*)d_in[2];
    const float* Wv = (const float*)d_in[3];
    const float* Wo = (const float*)d_in[4];
    float* out = (float*)d_out;

    __half *q, *k, *v, *att, *xh, *wh;
    cudaGetSymbolAddress((void**)&q,   g_qh);
    cudaGetSymbolAddress((void**)&k,   g_kh);
    cudaGetSymbolAddress((void**)&v,   g_vh);
    cudaGetSymbolAddress((void**)&att, g_atth);
    cudaGetSymbolAddress((void**)&xh,  g_xh);
    cudaGetSymbolAddress((void**)&wh,  g_wh);
    __half* wq = wh;
    __half* wk = wh + 1 * (size_t)D_MODEL * D_MODEL;
    __half* wv = wh + 2 * (size_t)D_MODEL * D_MODEL;
    __half* wo = wh + 3 * (size_t)D_MODEL * D_MODEL;

    cudaFuncSetAttribute(gemm_h<__half>,
                         cudaFuncAttributeMaxDynamicSharedMemorySize, HSMEM_BYTES);
    cudaFuncSetAttribute(gemm_h<float>,
                         cudaFuncAttributeMaxDynamicSharedMemorySize, HSMEM_BYTES);
    cudaFuncSetAttribute(attn_h,
                         cudaFuncAttributeMaxDynamicSharedMemorySize, ATTN_SMEM_BYTES);

    // fp32 -> fp16 prep, one launch (grid.y selects tensor)
    f2h5_kernel<<<dim3(NX8 / 256, 5), 256>>>(x, Wq, Wk, Wv, Wo, xh, wh);

    // Fused QKV projections (fp16 out)
    dim3 gq(D_MODEL / 128, M_ROWS / 128, 3);   // (8, 32, 3)
    gemm_h<__half><<<gq, 256, HSMEM_BYTES>>>(xh, wq, wk, wv, q, k, v,
                                             M_ROWS, D_MODEL, D_MODEL);

    attn_h<<<dim3(S_LEN / 128, NH, BATCH), 256, ATTN_SMEM_BYTES>>>(q, k, v, att);

    // O projection (fp32 out to d_out)
    dim3 go(D_MODEL / 128, M_ROWS / 128, 1);
    gemm_h<float><<<go, 256, HSMEM_BYTES>>>(att, wo, wo, wo, out, out, out,
                                            M_ROWS, D_MODEL, D_MODEL);
}